// round 2
// baseline (speedup 1.0000x reference)
#include <cuda_runtime.h>
#include <math.h>

#define HD 128
#define MAXN 100000

// Scratch (static device globals: allowed; runtime alloc is not)
__device__ float g_agg[MAXN * HD];
__device__ float g_h[MAXN * HD];
__device__ float g_x[MAXN * HD];
__device__ float g_stats[2 * HD];

__device__ __forceinline__ float gelu_exact(float v) {
    return 0.5f * v * (1.0f + erff(v * 0.70710678118654752440f));
}

__device__ __forceinline__ unsigned long long pack2(float lo, float hi) {
    unsigned long long r;
    asm("mov.b64 %0, {%1,%2};" : "=l"(r) : "f"(lo), "f"(hi));
    return r;
}
__device__ __forceinline__ float2 unpack2(unsigned long long v) {
    float2 r;
    asm("mov.b64 {%0,%1}, %2;" : "=f"(r.x), "=f"(r.y) : "l"(v));
    return r;
}
// Packed dual-FMA: full-rate fp32 on sm_103a (3-reg FFMA is half-rate)
__device__ __forceinline__ void ffma2(unsigned long long& d, unsigned long long a,
                                      unsigned long long b) {
    asm("fma.rn.f32x2 %0, %1, %2, %0;" : "+l"(d) : "l"(a), "l"(b));
}

// ---------------------------------------------------------------------------
// Zero agg buffer + stats
__global__ void zero_kernel(float4* __restrict__ agg4, float* __restrict__ stats, int n4) {
    int i = blockIdx.x * blockDim.x + threadIdx.x;
    if (i < n4) agg4[i] = make_float4(0.f, 0.f, 0.f, 0.f);
    if (i < 2 * HD) stats[i] = 0.f;
}

// ---------------------------------------------------------------------------
// Edge gather-scale-scatter: agg[dst] += x[src] * w   (one warp per edge)
__global__ void scatter_kernel(const float4* __restrict__ x4,
                               const int* __restrict__ ei,
                               const float* __restrict__ ea,
                               float* __restrict__ agg, int E) {
    long long t = (long long)blockIdx.x * blockDim.x + threadIdx.x;
    int e = (int)(t >> 5);
    if (e >= E) return;
    int lane = (int)(t & 31);
    int s = ei[e];
    int d = ei[E + e];
    float w = ea[e];
    float4 v = x4[(size_t)s * 32 + lane];
    v.x *= w; v.y *= w; v.z *= w; v.w *= w;
    float* p = agg + (size_t)d * HD + lane * 4;
    asm volatile("red.global.add.v4.f32 [%0], {%1,%2,%3,%4};"
                 :: "l"(p), "f"(v.x), "f"(v.y), "f"(v.z), "f"(v.w)
                 : "memory");
}

// ---------------------------------------------------------------------------
// Fused conv GEMM:  H = gelu(agg@B0 + x@B1 + bias), accumulating BN stats.
// Block tile 128x128, K = 256 (agg half then x half), 256 threads, 8x8/thread.
__global__ void __launch_bounds__(256, 2) conv_gemm(
    const float* __restrict__ A0, const float* __restrict__ A1,
    const float* __restrict__ B0, const float* __restrict__ B1,
    const float* __restrict__ bias,
    float* __restrict__ Hout, float* __restrict__ stats, int n) {
    __shared__ float As[8][HD];
    __shared__ float Bs[8][HD];
    __shared__ float s_sum[HD];
    __shared__ float s_sq[HD];

    int t = threadIdx.x;
    int tx = t & 15, ty = t >> 4;
    int row0 = blockIdx.x * 128;
    if (t < HD) { s_sum[t] = 0.f; s_sq[t] = 0.f; }

    unsigned long long acc[8][4];
#pragma unroll
    for (int i = 0; i < 8; i++)
#pragma unroll
        for (int j = 0; j < 4; j++) acc[i][j] = 0ull;

    int mA = t >> 1;
    int half = t & 1;
    int kB = t >> 5;
    int qB = t & 31;
    int grA = row0 + mA;
    bool va_ok = grA < n;

    for (int kt = 0; kt < 32; kt++) {
        int kcol = kt * 8 + half * 4;
        const float* Ap = (kcol < 128) ? A0 : A1;
        int ac = kcol & 127;
        float4 va = make_float4(0.f, 0.f, 0.f, 0.f);
        if (va_ok) va = *(const float4*)(Ap + (size_t)grA * HD + ac);
        int krow = kt * 8 + kB;
        const float* Bp = (krow < 128) ? B0 : B1;
        float4 vb = *(const float4*)(Bp + (size_t)(krow & 127) * HD + qB * 4);
        __syncthreads();
        As[half * 4 + 0][mA] = va.x;
        As[half * 4 + 1][mA] = va.y;
        As[half * 4 + 2][mA] = va.z;
        As[half * 4 + 3][mA] = va.w;
        *(float4*)&Bs[kB][qB * 4] = vb;
        __syncthreads();
#pragma unroll
        for (int kk = 0; kk < 8; kk++) {
            float4 a0 = *(const float4*)&As[kk][ty * 8];
            float4 a1 = *(const float4*)&As[kk][ty * 8 + 4];
            unsigned long long bb[4];
            bb[0] = *(const unsigned long long*)&Bs[kk][tx * 8 + 0];
            bb[1] = *(const unsigned long long*)&Bs[kk][tx * 8 + 2];
            bb[2] = *(const unsigned long long*)&Bs[kk][tx * 8 + 4];
            bb[3] = *(const unsigned long long*)&Bs[kk][tx * 8 + 6];
            float av[8] = {a0.x, a0.y, a0.z, a0.w, a1.x, a1.y, a1.z, a1.w};
#pragma unroll
            for (int i = 0; i < 8; i++) {
                unsigned long long aa = pack2(av[i], av[i]);
#pragma unroll
                for (int j = 0; j < 4; j++) ffma2(acc[i][j], aa, bb[j]);
            }
        }
    }

    // Epilogue: bias + GELU, write H, accumulate BN stats
    float bv[8];
#pragma unroll
    for (int j = 0; j < 8; j++) bv[j] = bias[tx * 8 + j];
    float csum[8], csq[8];
#pragma unroll
    for (int j = 0; j < 8; j++) { csum[j] = 0.f; csq[j] = 0.f; }
#pragma unroll
    for (int i = 0; i < 8; i++) {
        int gr = row0 + ty * 8 + i;
        if (gr >= n) break;
        float o[8];
#pragma unroll
        for (int j4 = 0; j4 < 4; j4++) {
            float2 p = unpack2(acc[i][j4]);
            o[2 * j4 + 0] = gelu_exact(p.x + bv[2 * j4 + 0]);
            o[2 * j4 + 1] = gelu_exact(p.y + bv[2 * j4 + 1]);
        }
#pragma unroll
        for (int j4 = 0; j4 < 4; j4++) {
            float2 w;
            w.x = o[2 * j4 + 0];
            w.y = o[2 * j4 + 1];
            *(float2*)&Hout[(size_t)gr * HD + tx * 8 + 2 * j4] = w;
        }
#pragma unroll
        for (int j = 0; j < 8; j++) {
            csum[j] += o[j];
            csq[j] += o[j] * o[j];
        }
    }
#pragma unroll
    for (int j = 0; j < 8; j++) {
        atomicAdd(&s_sum[tx * 8 + j], csum[j]);
        atomicAdd(&s_sq[tx * 8 + j], csq[j]);
    }
    __syncthreads();
    if (t < HD) {
        atomicAdd(&stats[t], s_sum[t]);
        atomicAdd(&stats[HD + t], s_sq[t]);
    }
}

// ---------------------------------------------------------------------------
// BatchNorm (training-mode batch stats) normalize: xout = (h-mean)*rsqrt(var+eps)*g + b
__global__ void bn_kernel(const float4* __restrict__ h4, const float* __restrict__ stats,
                          const float* __restrict__ g, const float* __restrict__ b,
                          float4* __restrict__ out4, int n) {
    int i = blockIdx.x * blockDim.x + threadIdx.x;
    int total = n * 32;
    if (i >= total) return;
    int c4 = i & 31;
    float invN = 1.0f / (float)n;
    float4 s = ((const float4*)stats)[c4];
    float4 q = ((const float4*)stats)[32 + c4];
    float4 gg = ((const float4*)g)[c4];
    float4 bb = ((const float4*)b)[c4];
    float m0 = s.x * invN, m1 = s.y * invN, m2 = s.z * invN, m3 = s.w * invN;
    float sc0 = rsqrtf(fmaxf(q.x * invN - m0 * m0, 0.f) + 1e-5f) * gg.x;
    float sc1 = rsqrtf(fmaxf(q.y * invN - m1 * m1, 0.f) + 1e-5f) * gg.y;
    float sc2 = rsqrtf(fmaxf(q.z * invN - m2 * m2, 0.f) + 1e-5f) * gg.z;
    float sc3 = rsqrtf(fmaxf(q.w * invN - m3 * m3, 0.f) + 1e-5f) * gg.w;
    float4 h = h4[i];
    float4 o;
    o.x = (h.x - m0) * sc0 + bb.x;
    o.y = (h.y - m1) * sc1 + bb.y;
    o.z = (h.z - m2) * sc2 + bb.z;
    o.w = (h.w - m3) * sc3 + bb.w;
    out4[i] = o;
}

// ---------------------------------------------------------------------------
// Fused edge MLP: gather [x[u]|x[v]] (K=256) @ W1 (256x128), +b1, GELU,
// dot with w2, +b2, sigmoid. Block = 128 edges, 256 threads, 8x8/thread.
__global__ void __launch_bounds__(256, 2) mlp_kernel(
    const float* __restrict__ X, const int* __restrict__ eli,
    const float* __restrict__ W1, const float* __restrict__ B1v,
    const float* __restrict__ W2, const float* __restrict__ B2,
    float* __restrict__ out, int EQ) {
    __shared__ float As[8][HD];
    __shared__ float Bs[8][HD];
    __shared__ int s_u[128];
    __shared__ int s_v[128];
    __shared__ float s_row[128];

    int t = threadIdx.x;
    int tx = t & 15, ty = t >> 4;
    int row0 = blockIdx.x * 128;
    if (t < 128) {
        int gr = row0 + t;
        int e = (gr < EQ) ? gr : 0;
        s_u[t] = eli[e];
        s_v[t] = eli[EQ + e];
        s_row[t] = 0.f;
    }
    __syncthreads();

    unsigned long long acc[8][4];
#pragma unroll
    for (int i = 0; i < 8; i++)
#pragma unroll
        for (int j = 0; j < 4; j++) acc[i][j] = 0ull;

    int mA = t >> 1;
    int half = t & 1;
    int kB = t >> 5;
    int qB = t & 31;

    for (int kt = 0; kt < 32; kt++) {
        int kcol = kt * 8 + half * 4;
        int node = (kcol < 128) ? s_u[mA] : s_v[mA];
        int ac = kcol & 127;
        float4 va = *(const float4*)(X + (size_t)node * HD + ac);
        int krow = kt * 8 + kB;
        float4 vb = *(const float4*)(W1 + (size_t)krow * HD + qB * 4);
        __syncthreads();
        As[half * 4 + 0][mA] = va.x;
        As[half * 4 + 1][mA] = va.y;
        As[half * 4 + 2][mA] = va.z;
        As[half * 4 + 3][mA] = va.w;
        *(float4*)&Bs[kB][qB * 4] = vb;
        __syncthreads();
#pragma unroll
        for (int kk = 0; kk < 8; kk++) {
            float4 a0 = *(const float4*)&As[kk][ty * 8];
            float4 a1 = *(const float4*)&As[kk][ty * 8 + 4];
            unsigned long long bb[4];
            bb[0] = *(const unsigned long long*)&Bs[kk][tx * 8 + 0];
            bb[1] = *(const unsigned long long*)&Bs[kk][tx * 8 + 2];
            bb[2] = *(const unsigned long long*)&Bs[kk][tx * 8 + 4];
            bb[3] = *(const unsigned long long*)&Bs[kk][tx * 8 + 6];
            float av[8] = {a0.x, a0.y, a0.z, a0.w, a1.x, a1.y, a1.z, a1.w};
#pragma unroll
            for (int i = 0; i < 8; i++) {
                unsigned long long aa = pack2(av[i], av[i]);
#pragma unroll
                for (int j = 0; j < 4; j++) ffma2(acc[i][j], aa, bb[j]);
            }
        }
    }

    // Epilogue: +b1, GELU, dot with w2 per row, reduce across column-threads
    float b1v[8], w2v[8];
#pragma unroll
    for (int j = 0; j < 8; j++) {
        b1v[j] = B1v[tx * 8 + j];
        w2v[j] = W2[tx * 8 + j];
    }
#pragma unroll
    for (int i = 0; i < 8; i++) {
        float p = 0.f;
#pragma unroll
        for (int j4 = 0; j4 < 4; j4++) {
            float2 pr = unpack2(acc[i][j4]);
            p += gelu_exact(pr.x + b1v[2 * j4 + 0]) * w2v[2 * j4 + 0];
            p += gelu_exact(pr.y + b1v[2 * j4 + 1]) * w2v[2 * j4 + 1];
        }
        atomicAdd(&s_row[ty * 8 + i], p);
    }
    __syncthreads();
    if (t < 128) {
        int gr = row0 + t;
        if (gr < EQ) {
            float z = s_row[t] + B2[0];
            out[gr] = 1.0f / (1.0f + expf(-z));
        }
    }
}

// ---------------------------------------------------------------------------
extern "C" void kernel_launch(void* const* d_in, const int* in_sizes, int n_in,
                              void* d_out, int out_size) {
    const float* x       = (const float*)d_in[0];
    const int*   ei      = (const int*)d_in[1];
    const float* ea      = (const float*)d_in[2];
    const int*   eli     = (const int*)d_in[3];
    const float* rel_w   = (const float*)d_in[4];
    const float* rel_b   = (const float*)d_in[5];
    const float* root_w  = (const float*)d_in[6];
    const float* bn_g    = (const float*)d_in[7];
    const float* bn_b    = (const float*)d_in[8];
    const float* w1      = (const float*)d_in[9];
    const float* b1      = (const float*)d_in[10];
    const float* w2      = (const float*)d_in[11];
    const float* b2      = (const float*)d_in[12];

    int N  = in_sizes[0] / HD;
    int E  = in_sizes[1] / 2;
    int EQ = in_sizes[3] / 2;
    int NC = in_sizes[4] / (HD * HD);

    float *agg, *hbuf, *xbuf, *stats;
    cudaGetSymbolAddress((void**)&agg,   g_agg);
    cudaGetSymbolAddress((void**)&hbuf,  g_h);
    cudaGetSymbolAddress((void**)&xbuf,  g_x);
    cudaGetSymbolAddress((void**)&stats, g_stats);

    int n4 = N * 32;
    int zb = (n4 + 255) / 256;
    long long st = (long long)E * 32;
    int sb = (int)((st + 255) / 256);
    int gb = (N + 127) / 128;
    int mb = (EQ + 127) / 128;

    const float* xcur = x;
    for (int l = 0; l < NC; l++) {
        zero_kernel<<<zb, 256>>>((float4*)agg, stats, n4);
        scatter_kernel<<<sb, 256>>>((const float4*)xcur, ei, ea, agg, E);
        conv_gemm<<<gb, 256>>>(agg, xcur,
                               rel_w + (size_t)l * HD * HD,
                               root_w + (size_t)l * HD * HD,
                               rel_b + (size_t)l * HD,
                               hbuf, stats, N);
        bn_kernel<<<zb, 256>>>((const float4*)hbuf, stats,
                               bn_g + (size_t)l * HD, bn_b + (size_t)l * HD,
                               (float4*)xbuf, N);
        xcur = xbuf;
    }
    mlp_kernel<<<mb, 256>>>(xbuf, eli, w1, b1, w2, b2, (float*)d_out, EQ);
}

// round 4
// speedup vs baseline: 1.3651x; 1.3651x over previous
#include <cuda_runtime.h>
#include <cuda_bf16.h>
#include <math.h>
#include <stdint.h>

#define HD 128
#define MAXN 100000
#define NCMAX 4

// Scratch (static device globals: allowed; runtime alloc is not)
__device__ float g_agg[MAXN * HD];
__device__ float g_h[MAXN * HD];
__device__ float g_x[MAXN * HD];
__device__ float g_stats[2 * HD];
// conv weights transposed+split: [l][mat(rel/root)][hi/lo][n=128][k=128]
__device__ __nv_bfloat16 g_wtc[NCMAX * 2 * 2 * HD * HD];
// mlp W1 transposed+split: [hi/lo][n=128][k=256]
__device__ __nv_bfloat16 g_wt1[2 * HD * 2 * HD];

// Smem layout (conv):  0: bias(512) | 1024: Ahi | +22528: Alo | Bhi | Blo
#define PITCH 176
#define AREG (128 * PITCH)  // 22528
#define CONV_A 1024
#define CONV_SMEM (CONV_A + 4 * AREG)  // 91136
// Smem layout (mlp): 0: b1 | 512: w2 | 1024: s_row | 1536: idx_u | 2048: idx_v | 2560: A/B
#define MLP_A 2560
#define MLP_SMEM (MLP_A + 4 * AREG)  // 92672

__device__ __forceinline__ float gelu_exact(float v) {
    return 0.5f * v * (1.0f + erff(v * 0.70710678118654752440f));
}
__device__ __forceinline__ uint32_t smem_u32(const void* p) {
    uint32_t a;
    asm("{ .reg .u64 t; cvta.to.shared.u64 t, %1; cvt.u32.u64 %0, t; }" : "=r"(a) : "l"(p));
    return a;
}
__device__ __forceinline__ uint32_t bfbits(__nv_bfloat16 h) {
    return (uint32_t)__bfloat16_as_ushort(h);
}
__device__ __forceinline__ void ldmx4(uint32_t* r, uint32_t addr) {
    asm volatile("ldmatrix.sync.aligned.m8n8.x4.shared.b16 {%0,%1,%2,%3}, [%4];"
                 : "=r"(r[0]), "=r"(r[1]), "=r"(r[2]), "=r"(r[3]) : "r"(addr));
}
__device__ __forceinline__ void mma_bf16(float* c, const uint32_t* a, const uint32_t* b) {
    asm volatile(
        "mma.sync.aligned.m16n8k16.row.col.f32.bf16.bf16.f32 "
        "{%0,%1,%2,%3},{%4,%5,%6,%7},{%8,%9},{%0,%1,%2,%3};"
        : "+f"(c[0]), "+f"(c[1]), "+f"(c[2]), "+f"(c[3])
        : "r"(a[0]), "r"(a[1]), "r"(a[2]), "r"(a[3]), "r"(b[0]), "r"(b[1]));
}
// split fp32 -> bf16 hi/lo pair packed as two b32 (2 elems each)
__device__ __forceinline__ void split2(float x, float y, uint32_t& hi, uint32_t& lo) {
    __nv_bfloat16 hx = __float2bfloat16(x), hy = __float2bfloat16(y);
    __nv_bfloat16 lx = __float2bfloat16(x - __bfloat162float(hx));
    __nv_bfloat16 ly = __float2bfloat16(y - __bfloat162float(hy));
    hi = bfbits(hx) | (bfbits(hy) << 16);
    lo = bfbits(lx) | (bfbits(ly) << 16);
}

// ---------------------------------------------------------------------------
__global__ void zero_kernel(float4* __restrict__ agg4, float* __restrict__ stats, int n4) {
    int i = blockIdx.x * blockDim.x + threadIdx.x;
    if (i < n4) agg4[i] = make_float4(0.f, 0.f, 0.f, 0.f);
    if (i < 2 * HD) stats[i] = 0.f;
}

// ---------------------------------------------------------------------------
// Edge gather-scale-scatter: agg[dst] += x[src] * w   (one warp per edge)
__global__ void scatter_kernel(const float4* __restrict__ x4,
                               const int* __restrict__ ei,
                               const float* __restrict__ ea,
                               float* __restrict__ agg, int E) {
    long long t = (long long)blockIdx.x * blockDim.x + threadIdx.x;
    int e = (int)(t >> 5);
    if (e >= E) return;
    int lane = (int)(t & 31);
    int s = ei[e];
    int d = ei[E + e];
    float w = ea[e];
    float4 v = x4[(size_t)s * 32 + lane];
    v.x *= w; v.y *= w; v.z *= w; v.w *= w;
    float* p = agg + (size_t)d * HD + lane * 4;
    asm volatile("red.global.add.v4.f32 [%0], {%1,%2,%3,%4};"
                 :: "l"(p), "f"(v.x), "f"(v.y), "f"(v.z), "f"(v.w) : "memory");
}

// ---------------------------------------------------------------------------
// Weight prep: transpose + bf16 hi/lo split (runs once per launch)
__global__ void prep_w(const float* __restrict__ rel_w, const float* __restrict__ root_w,
                       const float* __restrict__ w1, int NC) {
    int idx = blockIdx.x * 256 + threadIdx.x;
    int convTotal = NC * 2 * HD * HD;
    if (idx < convTotal) {
        int l = idx / (2 * HD * HD);
        int rem = idx % (2 * HD * HD);
        int m = rem / (HD * HD);
        int r = rem % (HD * HD);
        int k = r >> 7, nn = r & 127;
        const float* W = m ? root_w : rel_w;
        float v = W[(size_t)l * HD * HD + k * HD + nn];
        __nv_bfloat16 hi = __float2bfloat16(v);
        __nv_bfloat16 lo = __float2bfloat16(v - __bfloat162float(hi));
        size_t base = ((size_t)(l * 2 + m) * 2) * HD * HD;
        g_wtc[base + nn * HD + k] = hi;
        g_wtc[base + HD * HD + nn * HD + k] = lo;
    } else if (idx < convTotal + 2 * HD * HD) {
        int r = idx - convTotal;
        int k = r >> 7, nn = r & 127;  // k in 0..255
        float v = w1[(size_t)k * HD + nn];
        __nv_bfloat16 hi = __float2bfloat16(v);
        __nv_bfloat16 lo = __float2bfloat16(v - __bfloat162float(hi));
        g_wt1[(size_t)nn * 256 + k] = hi;
        g_wt1[(size_t)HD * 2 * HD + nn * 256 + k] = lo;
    }
}

// ---------------------------------------------------------------------------
// HMMA conv GEMM: H = gelu(agg@relW + x@rootW + bias) via bf16 2-term split.
// 128x128 CTA tile, 8 warps (2 m x 4 n), warp tile 64x32, K chunks of 64.
__global__ void __launch_bounds__(256, 2) conv_mma(
    const float* __restrict__ A0, const float* __restrict__ A1,
    const __nv_bfloat16* __restrict__ Wr_hi, const __nv_bfloat16* __restrict__ Wr_lo,
    const __nv_bfloat16* __restrict__ Wo_hi, const __nv_bfloat16* __restrict__ Wo_lo,
    const float* __restrict__ bias, float* __restrict__ Hout, int n) {
    extern __shared__ __align__(16) char smp[];
    uint32_t sm = smem_u32(smp);
    int t = threadIdx.x, wid = t >> 5, lane = t & 31;
    int row0 = blockIdx.x * 128;
    int mbase = (wid & 1) * 64, nbase = (wid >> 1) * 32;

    if (t < HD) *(float*)(smp + t * 4) = bias[t];

    float c[4][4][4];
#pragma unroll
    for (int i = 0; i < 4; i++)
#pragma unroll
        for (int j = 0; j < 4; j++)
#pragma unroll
            for (int q = 0; q < 4; q++) c[i][j][q] = 0.f;

    // per-lane ldmatrix address components
    int sub = lane >> 3, r8 = lane & 7;
    uint32_t laneA = (uint32_t)((mbase + r8 + (sub & 1) * 8) * PITCH + (sub >> 1) * 16);
    uint32_t laneB = (uint32_t)((nbase + (sub >> 1) * 8 + r8) * PITCH + (sub & 1) * 16);

    int rq = t & 15, rr = t >> 4;

    for (int ch = 0; ch < 4; ch++) {
        const float* A = (ch < 2) ? A0 : A1;
        const __nv_bfloat16* Bh = (ch < 2) ? Wr_hi : Wo_hi;
        const __nv_bfloat16* Bl = (ch < 2) ? Wr_lo : Wo_lo;
        int ko = (ch & 1) * 64;
        __syncthreads();
        // stage A: 128 rows x 64 k fp32 -> bf16 hi/lo
#pragma unroll
        for (int p = 0; p < 8; p++) {
            int row = p * 16 + rr;
            int grow = row0 + row;
            float4 v = make_float4(0.f, 0.f, 0.f, 0.f);
            if (grow < n) v = *(const float4*)(A + (size_t)grow * HD + ko + rq * 4);
            uint32_t h0, l0, h1, l1;
            split2(v.x, v.y, h0, l0);
            split2(v.z, v.w, h1, l1);
            uint32_t off = (uint32_t)(row * PITCH + rq * 8);
            *(uint2*)(smp + CONV_A + off) = make_uint2(h0, h1);
            *(uint2*)(smp + CONV_A + AREG + off) = make_uint2(l0, l1);
        }
        // stage B: 128 n x 64 k bf16 hi/lo (pre-split)
#pragma unroll
        for (int p = 0; p < 4; p++) {
            int lin = p * 256 + t;
            int nn = lin >> 3, q = lin & 7;
            uint32_t off = (uint32_t)(nn * PITCH + q * 16);
            *(uint4*)(smp + CONV_A + 2 * AREG + off) =
                *(const uint4*)(Bh + (size_t)nn * HD + ko + q * 8);
            *(uint4*)(smp + CONV_A + 3 * AREG + off) =
                *(const uint4*)(Bl + (size_t)nn * HD + ko + q * 8);
        }
        __syncthreads();
        // 3 passes: Ah*Bh, Al*Bh, Ah*Bl
#pragma unroll
        for (int ps = 0; ps < 3; ps++) {
            uint32_t Ab = sm + CONV_A + ((ps == 1) ? AREG : 0) + laneA;
            uint32_t Bb = sm + CONV_A + 2 * AREG + ((ps == 2) ? AREG : 0) + laneB;
#pragma unroll
            for (int ks = 0; ks < 4; ks++) {
                uint32_t a[4][4], b[8];
#pragma unroll
                for (int mt = 0; mt < 4; mt++)
                    ldmx4(a[mt], Ab + mt * (16 * PITCH) + ks * 32);
#pragma unroll
                for (int bp = 0; bp < 2; bp++)
                    ldmx4(b + bp * 4, Bb + bp * (16 * PITCH) + ks * 32);
#pragma unroll
                for (int mt = 0; mt < 4; mt++)
#pragma unroll
                    for (int nt = 0; nt < 4; nt++)
                        mma_bf16(c[mt][nt], a[mt], b + nt * 2);
            }
        }
    }

    // Epilogue: +bias, gelu, store
    int g = lane >> 2, tq = lane & 3;
#pragma unroll
    for (int mt = 0; mt < 4; mt++) {
        int lr0 = mbase + mt * 16 + g;
        int gr0 = row0 + lr0, gr1 = gr0 + 8;
#pragma unroll
        for (int nt = 0; nt < 4; nt++) {
            int cb = nbase + nt * 8 + tq * 2;
            float2 bv = *(float2*)(smp + cb * 4);
            if (gr0 < n) {
                float2 o;
                o.x = gelu_exact(c[mt][nt][0] + bv.x);
                o.y = gelu_exact(c[mt][nt][1] + bv.y);
                *(float2*)(Hout + (size_t)gr0 * HD + cb) = o;
            }
            if (gr1 < n) {
                float2 o;
                o.x = gelu_exact(c[mt][nt][2] + bv.x);
                o.y = gelu_exact(c[mt][nt][3] + bv.y);
                *(float2*)(Hout + (size_t)gr1 * HD + cb) = o;
            }
        }
    }
}

// ---------------------------------------------------------------------------
// BN stats: column sums + sumsq over Hout
__global__ void stats_kernel(const float* __restrict__ H, float* __restrict__ stats, int n) {
    __shared__ float ss[HD], sq[HD];
    int t = threadIdx.x;
    if (t < HD) { ss[t] = 0.f; sq[t] = 0.f; }
    __syncthreads();
    int cg = t & 31, rl = t >> 5;
    float4 s = make_float4(0.f, 0.f, 0.f, 0.f);
    float4 q = make_float4(0.f, 0.f, 0.f, 0.f);
    for (int r = blockIdx.x * 8 + rl; r < n; r += gridDim.x * 8) {
        float4 v = ((const float4*)H)[(size_t)r * 32 + cg];
        s.x += v.x; s.y += v.y; s.z += v.z; s.w += v.w;
        q.x += v.x * v.x; q.y += v.y * v.y; q.z += v.z * v.z; q.w += v.w * v.w;
    }
    atomicAdd(&ss[cg * 4 + 0], s.x); atomicAdd(&ss[cg * 4 + 1], s.y);
    atomicAdd(&ss[cg * 4 + 2], s.z); atomicAdd(&ss[cg * 4 + 3], s.w);
    atomicAdd(&sq[cg * 4 + 0], q.x); atomicAdd(&sq[cg * 4 + 1], q.y);
    atomicAdd(&sq[cg * 4 + 2], q.z); atomicAdd(&sq[cg * 4 + 3], q.w);
    __syncthreads();
    if (t < HD) {
        atomicAdd(&stats[t], ss[t]);
        atomicAdd(&stats[HD + t], sq[t]);
    }
}

// ---------------------------------------------------------------------------
__global__ void bn_kernel(const float4* __restrict__ h4, const float* __restrict__ stats,
                          const float* __restrict__ g, const float* __restrict__ b,
                          float4* __restrict__ out4, int n) {
    int i = blockIdx.x * blockDim.x + threadIdx.x;
    int total = n * 32;
    if (i >= total) return;
    int c4 = i & 31;
    float invN = 1.0f / (float)n;
    float4 s = ((const float4*)stats)[c4];
    float4 q = ((const float4*)stats)[32 + c4];
    float4 gg = ((const float4*)g)[c4];
    float4 bb = ((const float4*)b)[c4];
    float m0 = s.x * invN, m1 = s.y * invN, m2 = s.z * invN, m3 = s.w * invN;
    float sc0 = rsqrtf(fmaxf(q.x * invN - m0 * m0, 0.f) + 1e-5f) * gg.x;
    float sc1 = rsqrtf(fmaxf(q.y * invN - m1 * m1, 0.f) + 1e-5f) * gg.y;
    float sc2 = rsqrtf(fmaxf(q.z * invN - m2 * m2, 0.f) + 1e-5f) * gg.z;
    float sc3 = rsqrtf(fmaxf(q.w * invN - m3 * m3, 0.f) + 1e-5f) * gg.w;
    float4 h = h4[i];
    float4 o;
    o.x = (h.x - m0) * sc0 + bb.x;
    o.y = (h.y - m1) * sc1 + bb.y;
    o.z = (h.z - m2) * sc2 + bb.z;
    o.w = (h.w - m3) * sc3 + bb.w;
    out4[i] = o;
}

// ---------------------------------------------------------------------------
// HMMA edge MLP: D = [x[u]|x[v]] @ W1 (split), epi: gelu(+b1) dot w2, sigmoid
__global__ void __launch_bounds__(256, 2) mlp_mma(
    const float* __restrict__ X, const int* __restrict__ eli,
    const __nv_bfloat16* __restrict__ W1h, const __nv_bfloat16* __restrict__ W1l,
    const float* __restrict__ B1, const float* __restrict__ W2,
    const float* __restrict__ B2, float* __restrict__ out, int EQ) {
    extern __shared__ __align__(16) char smp[];
    uint32_t sm = smem_u32(smp);
    int t = threadIdx.x, wid = t >> 5, lane = t & 31;
    int row0 = blockIdx.x * 128;
    int mbase = (wid & 1) * 64, nbase = (wid >> 1) * 32;

    if (t < HD) {
        *(float*)(smp + t * 4) = B1[t];
        *(float*)(smp + 512 + t * 4) = W2[t];
        *(float*)(smp + 1024 + t * 4) = 0.f;
        int gr = row0 + t;
        int e = (gr < EQ) ? gr : 0;
        *(int*)(smp + 1536 + t * 4) = eli[e];
        *(int*)(smp + 2048 + t * 4) = eli[EQ + e];
    }

    float c[4][4][4];
#pragma unroll
    for (int i = 0; i < 4; i++)
#pragma unroll
        for (int j = 0; j < 4; j++)
#pragma unroll
            for (int q = 0; q < 4; q++) c[i][j][q] = 0.f;

    int sub = lane >> 3, r8 = lane & 7;
    uint32_t laneA = (uint32_t)((mbase + r8 + (sub & 1) * 8) * PITCH + (sub >> 1) * 16);
    uint32_t laneB = (uint32_t)((nbase + (sub >> 1) * 8 + r8) * PITCH + (sub & 1) * 16);

    int rq = t & 15, rr = t >> 4;

    for (int ch = 0; ch < 4; ch++) {
        int idxOff = (ch < 2) ? 1536 : 2048;
        int ko = (ch & 1) * 64;
        __syncthreads();
#pragma unroll
        for (int p = 0; p < 8; p++) {
            int row = p * 16 + rr;
            int node = *(const int*)(smp + idxOff + row * 4);
            float4 v = *(const float4*)(X + (size_t)node * HD + ko + rq * 4);
            uint32_t h0, l0, h1, l1;
            split2(v.x, v.y, h0, l0);
            split2(v.z, v.w, h1, l1);
            uint32_t off = (uint32_t)(row * PITCH + rq * 8);
            *(uint2*)(smp + MLP_A + off) = make_uint2(h0, h1);
            *(uint2*)(smp + MLP_A + AREG + off) = make_uint2(l0, l1);
        }
#pragma unroll
        for (int p = 0; p < 4; p++) {
            int lin = p * 256 + t;
            int nn = lin >> 3, q = lin & 7;
            uint32_t off = (uint32_t)(nn * PITCH + q * 16);
            *(uint4*)(smp + MLP_A + 2 * AREG + off) =
                *(const uint4*)(W1h + (size_t)nn * 256 + ch * 64 + q * 8);
            *(uint4*)(smp + MLP_A + 3 * AREG + off) =
                *(const uint4*)(W1l + (size_t)nn * 256 + ch * 64 + q * 8);
        }
        __syncthreads();
#pragma unroll
        for (int ps = 0; ps < 3; ps++) {
            uint32_t Ab = sm + MLP_A + ((ps == 1) ? AREG : 0) + laneA;
            uint32_t Bb = sm + MLP_A + 2 * AREG + ((ps == 2) ? AREG : 0) + laneB;
#pragma unroll
            for (int ks = 0; ks < 4; ks++) {
                uint32_t a[4][4], b[8];
#pragma unroll
                for (int mt = 0; mt < 4; mt++)
                    ldmx4(a[mt], Ab + mt * (16 * PITCH) + ks * 32);
#pragma unroll
                for (int bp = 0; bp < 2; bp++)
                    ldmx4(b + bp * 4, Bb + bp * (16 * PITCH) + ks * 32);
#pragma unroll
                for (int mt = 0; mt < 4; mt++)
#pragma unroll
                    for (int nt = 0; nt < 4; nt++)
                        mma_bf16(c[mt][nt], a[mt], b + nt * 2);
            }
        }
    }

    // Epilogue: gelu(+b1) dot w2 -> per-row partials -> sigmoid
    int g = lane >> 2, tq = lane & 3;
#pragma unroll
    for (int mt = 0; mt < 4; mt++) {
        float p0 = 0.f, p1 = 0.f;
#pragma unroll
        for (int nt = 0; nt < 4; nt++) {
            int cb = nbase + nt * 8 + tq * 2;
            float2 bv = *(float2*)(smp + cb * 4);
            float2 wv = *(float2*)(smp + 512 + cb * 4);
            p0 += gelu_exact(c[mt][nt][0] + bv.x) * wv.x
                + gelu_exact(c[mt][nt][1] + bv.y) * wv.y;
            p1 += gelu_exact(c[mt][nt][2] + bv.x) * wv.x
                + gelu_exact(c[mt][nt][3] + bv.y) * wv.y;
        }
        p0 += __shfl_xor_sync(0xFFFFFFFF, p0, 1);
        p0 += __shfl_xor_sync(0xFFFFFFFF, p0, 2);
        p1 += __shfl_xor_sync(0xFFFFFFFF, p1, 1);
        p1 += __shfl_xor_sync(0xFFFFFFFF, p1, 2);
        if (tq == 0) {
            int lr = mbase + mt * 16 + g;
            atomicAdd((float*)(smp + 1024 + lr * 4), p0);
            atomicAdd((float*)(smp + 1024 + (lr + 8) * 4), p1);
        }
    }
    __syncthreads();
    if (t < 128) {
        int gr = row0 + t;
        if (gr < EQ) {
            float z = *(float*)(smp + 1024 + t * 4) + B2[0];
            out[gr] = 1.0f / (1.0f + expf(-z));
        }
    }
}

// ---------------------------------------------------------------------------
extern "C" void kernel_launch(void* const* d_in, const int* in_sizes, int n_in,
                              void* d_out, int out_size) {
    const float* x      = (const float*)d_in[0];
    const int*   ei     = (const int*)d_in[1];
    const float* ea     = (const float*)d_in[2];
    const int*   eli    = (const int*)d_in[3];
    const float* rel_w  = (const float*)d_in[4];
    const float* rel_b  = (const float*)d_in[5];
    const float* root_w = (const float*)d_in[6];
    const float* bn_g   = (const float*)d_in[7];
    const float* bn_b   = (const float*)d_in[8];
    const float* w1     = (const float*)d_in[9];
    const float* b1     = (const float*)d_in[10];
    const float* w2     = (const float*)d_in[11];
    const float* b2     = (const float*)d_in[12];

    int N  = in_sizes[0] / HD;
    int E  = in_sizes[1] / 2;
    int EQ = in_sizes[3] / 2;
    int NC = in_sizes[4] / (HD * HD);

    float *agg, *hbuf, *xbuf, *stats;
    __nv_bfloat16 *wtc, *wt1;
    cudaGetSymbolAddress((void**)&agg,   g_agg);
    cudaGetSymbolAddress((void**)&hbuf,  g_h);
    cudaGetSymbolAddress((void**)&xbuf,  g_x);
    cudaGetSymbolAddress((void**)&stats, g_stats);
    cudaGetSymbolAddress((void**)&wtc,   g_wtc);
    cudaGetSymbolAddress((void**)&wt1,   g_wt1);

    cudaFuncSetAttribute(conv_mma, cudaFuncAttributeMaxDynamicSharedMemorySize, CONV_SMEM);
    cudaFuncSetAttribute(mlp_mma,  cudaFuncAttributeMaxDynamicSharedMemorySize, MLP_SMEM);

    int n4 = N * 32;
    int zb = (n4 + 255) / 256;
    long long st = (long long)E * 32;
    int sb = (int)((st + 255) / 256);
    int gb = (N + 127) / 128;
    int mb = (EQ + 127) / 128;
    int pb = (NC * 2 * HD * HD + 2 * HD * HD + 255) / 256;

    prep_w<<<pb, 256>>>(rel_w, root_w, w1, NC);

    const float* xcur = x;
    for (int l = 0; l < NC; l++) {
        zero_kernel<<<zb, 256>>>((float4*)agg, stats, n4);
        scatter_kernel<<<sb, 256>>>((const float4*)xcur, ei, ea, agg, E);
        size_t wb = (size_t)(l * 2) * 2 * HD * HD;
        conv_mma<<<gb, 256, CONV_SMEM>>>(agg, xcur,
                                         wtc + wb, wtc + wb + HD * HD,
                                         wtc + wb + 2 * HD * HD, wtc + wb + 3 * HD * HD,
                                         rel_b + (size_t)l * HD, hbuf, N);
        stats_kernel<<<256, 256>>>(hbuf, stats, N);
        bn_kernel<<<zb, 256>>>((const float4*)hbuf, stats,
                               bn_g + (size_t)l * HD, bn_b + (size_t)l * HD,
                               (float4*)xbuf, N);
        xcur = xbuf;
    }
    mlp_mma<<<mb, 256, MLP_SMEM>>>(xbuf, eli, wt1, wt1 + (size_t)HD * 2 * HD,
                                   b1, w2, b2, (float*)d_out, EQ);
}

// round 5
// speedup vs baseline: 2.0284x; 1.4859x over previous
#include <cuda_runtime.h>
#include <cuda_bf16.h>
#include <math.h>
#include <stdint.h>

#define HD 128
#define MAXN 100000
#define MAXE 600000
#define NCMAX 4

// ---------------- scratch globals ----------------
__device__ float g_h[MAXN * HD];
__device__ float g_x[MAXN * HD];
__device__ float g_stats[2 * HD];
__device__ __nv_bfloat16 g_agg_hi[MAXN * HD];
__device__ __nv_bfloat16 g_agg_lo[MAXN * HD];
__device__ __nv_bfloat16 g_xhi[MAXN * HD];
__device__ __nv_bfloat16 g_xlo[MAXN * HD];
__device__ int g_deg[MAXN];
__device__ int g_tmp[MAXN + 1024];
__device__ int g_part[128];
__device__ int g_rowptr[MAXN + 1];
__device__ int g_cursor[MAXN];
__device__ int g_csrc[MAXE];
__device__ float g_csw[MAXE];
__device__ __nv_bfloat16 g_wtc[NCMAX * 2 * 2 * HD * HD];
__device__ __nv_bfloat16 g_wt1[2 * HD * 2 * HD];

// ---------------- tiling constants ----------------
#define PITCH 176
#define TILE (128 * PITCH)      // 22528
#define BUF (2 * TILE)          // 45056: A tile + B tile
#define STATS_OFF (2 * BUF)     // 90112
#define CONV_SMEM (STATS_OFF + 1024)  // 91136
#define MLP_A 2560
#define MLP_SMEM (MLP_A + 4 * TILE)   // 92672

__device__ __forceinline__ float gelu_exact(float v) {
    return 0.5f * v * (1.0f + erff(v * 0.70710678118654752440f));
}
__device__ __forceinline__ uint32_t smem_u32(const void* p) {
    uint32_t a;
    asm("{ .reg .u64 t; cvta.to.shared.u64 t, %1; cvt.u32.u64 %0, t; }" : "=r"(a) : "l"(p));
    return a;
}
__device__ __forceinline__ uint32_t bfbits(__nv_bfloat16 h) {
    return (uint32_t)__bfloat16_as_ushort(h);
}
__device__ __forceinline__ void split2(float x, float y, uint32_t& hi, uint32_t& lo) {
    __nv_bfloat16 hx = __float2bfloat16(x), hy = __float2bfloat16(y);
    __nv_bfloat16 lx = __float2bfloat16(x - __bfloat162float(hx));
    __nv_bfloat16 ly = __float2bfloat16(y - __bfloat162float(hy));
    hi = bfbits(hx) | (bfbits(hy) << 16);
    lo = bfbits(lx) | (bfbits(ly) << 16);
}
__device__ __forceinline__ void ldmx4(uint32_t* r, uint32_t addr) {
    asm volatile("ldmatrix.sync.aligned.m8n8.x4.shared.b16 {%0,%1,%2,%3}, [%4];"
                 : "=r"(r[0]), "=r"(r[1]), "=r"(r[2]), "=r"(r[3]) : "r"(addr));
}
__device__ __forceinline__ void mma_bf16(float* c, const uint32_t* a, const uint32_t* b) {
    asm volatile(
        "mma.sync.aligned.m16n8k16.row.col.f32.bf16.bf16.f32 "
        "{%0,%1,%2,%3},{%4,%5,%6,%7},{%8,%9},{%0,%1,%2,%3};"
        : "+f"(c[0]), "+f"(c[1]), "+f"(c[2]), "+f"(c[3])
        : "r"(a[0]), "r"(a[1]), "r"(a[2]), "r"(a[3]), "r"(b[0]), "r"(b[1]));
}
__device__ __forceinline__ void cp16(uint32_t dst, const void* src, int sz) {
    asm volatile("cp.async.cg.shared.global [%0], [%1], 16, %2;"
                 :: "r"(dst), "l"(src), "r"(sz) : "memory");
}
__device__ __forceinline__ void cp_commit() {
    asm volatile("cp.async.commit_group;" ::: "memory");
}

// ---------------- CSR build ----------------
__global__ void zero_deg(int* deg, int n) {
    int i = blockIdx.x * 256 + threadIdx.x;
    if (i < n) deg[i] = 0;
}
__global__ void hist_kernel(const int* __restrict__ ei, int* __restrict__ deg, int E) {
    int e = blockIdx.x * 256 + threadIdx.x;
    if (e < E) atomicAdd(&deg[ei[E + e]], 1);
}
__global__ void scan1(const int* __restrict__ deg, int* __restrict__ tmp,
                      int* __restrict__ part, int n) {
    __shared__ int warpsum[8];
    int b = blockIdx.x, t = threadIdx.x;
    int base = b * 1024 + t * 4;
    int v0 = (base + 0 < n) ? deg[base + 0] : 0;
    int v1 = (base + 1 < n) ? deg[base + 1] : 0;
    int v2 = (base + 2 < n) ? deg[base + 2] : 0;
    int v3 = (base + 3 < n) ? deg[base + 3] : 0;
    int s0 = v0, s1 = s0 + v1, s2 = s1 + v2, s3 = s2 + v3;
    int tot = s3;
#pragma unroll
    for (int d = 1; d < 32; d <<= 1) {
        int u = __shfl_up_sync(0xFFFFFFFF, tot, d);
        if ((t & 31) >= d) tot += u;
    }
    if ((t & 31) == 31) warpsum[t >> 5] = tot;
    __syncthreads();
    if (t == 0) {
        int r = 0;
#pragma unroll
        for (int i = 0; i < 8; i++) { int x = warpsum[i]; warpsum[i] = r; r += x; }
        part[b] = r;
    }
    __syncthreads();
    int excl = warpsum[t >> 5] + (tot - s3);
    if (base + 0 <= n) tmp[base + 0] = excl;
    if (base + 1 <= n) tmp[base + 1] = excl + s0;
    if (base + 2 <= n) tmp[base + 2] = excl + s1;
    if (base + 3 <= n) tmp[base + 3] = excl + s2;
}
__global__ void scan2(int* part, int nb) {
    if (threadIdx.x == 0) {
        int r = 0;
        for (int i = 0; i < nb; i++) { int x = part[i]; part[i] = r; r += x; }
    }
}
__global__ void scan3(const int* __restrict__ tmp, const int* __restrict__ part,
                      int* __restrict__ rowptr, int* __restrict__ cursor, int n, int E) {
    int i = blockIdx.x * 256 + threadIdx.x;
    if (i < n) {
        int v = tmp[i] + part[i >> 10];
        rowptr[i] = v;
        cursor[i] = v;
    }
    if (i == n) rowptr[n] = E;
}
__global__ void fill_csr(const int* __restrict__ ei, const float* __restrict__ ea,
                         int* __restrict__ cursor, int* __restrict__ csrc,
                         float* __restrict__ csw, int E) {
    int e = blockIdx.x * 256 + threadIdx.x;
    if (e >= E) return;
    int d = ei[E + e];
    int pos = atomicAdd(&cursor[d], 1);
    csrc[pos] = ei[e];
    csw[pos] = ea[e];
}

// ---------------- producers: split conversions ----------------
__global__ void split_x(const float4* __restrict__ x4, uint2* __restrict__ xhi,
                        uint2* __restrict__ xlo, int n32) {
    int i = blockIdx.x * 256 + threadIdx.x;
    if (i >= n32) return;
    float4 v = x4[i];
    uint32_t h0, l0, h1, l1;
    split2(v.x, v.y, h0, l0);
    split2(v.z, v.w, h1, l1);
    xhi[i] = make_uint2(h0, h1);
    xlo[i] = make_uint2(l0, l1);
}

// ---------------- CSR aggregation: warp per node, no atomics ----------------
__global__ void agg_kernel(const float4* __restrict__ x4, const int* __restrict__ rowptr,
                           const int* __restrict__ csrc, const float* __restrict__ csw,
                           uint2* __restrict__ ahi, uint2* __restrict__ alo,
                           float* __restrict__ stats, int nn) {
    if (blockIdx.x == 0 && threadIdx.x < 2 * HD) stats[threadIdx.x] = 0.f;
    int node = (blockIdx.x * blockDim.x + threadIdx.x) >> 5;
    int lane = threadIdx.x & 31;
    if (node >= nn) return;
    int beg = rowptr[node], end = rowptr[node + 1];
    float4 acc = make_float4(0.f, 0.f, 0.f, 0.f);
    for (int e = beg; e < end; e++) {
        int s = __ldg(&csrc[e]);
        float w = __ldg(&csw[e]);
        float4 v = x4[(size_t)s * 32 + lane];
        acc.x += v.x * w; acc.y += v.y * w; acc.z += v.z * w; acc.w += v.w * w;
    }
    uint32_t h0, l0, h1, l1;
    split2(acc.x, acc.y, h0, l0);
    split2(acc.z, acc.w, h1, l1);
    ahi[(size_t)node * 32 + lane] = make_uint2(h0, h1);
    alo[(size_t)node * 32 + lane] = make_uint2(l0, l1);
}

// ---------------- weight prep (transpose + split) ----------------
__global__ void prep_w(const float* __restrict__ rel_w, const float* __restrict__ root_w,
                       const float* __restrict__ w1, int NC) {
    int idx = blockIdx.x * 256 + threadIdx.x;
    int convTotal = NC * 2 * HD * HD;
    if (idx < convTotal) {
        int l = idx / (2 * HD * HD);
        int rem = idx % (2 * HD * HD);
        int m = rem / (HD * HD);
        int r = rem % (HD * HD);
        int k = r >> 7, nn = r & 127;
        const float* W = m ? root_w : rel_w;
        float v = W[(size_t)l * HD * HD + k * HD + nn];
        __nv_bfloat16 hi = __float2bfloat16(v);
        __nv_bfloat16 lo = __float2bfloat16(v - __bfloat162float(hi));
        size_t base = ((size_t)(l * 2 + m) * 2) * HD * HD;
        g_wtc[base + nn * HD + k] = hi;
        g_wtc[base + HD * HD + nn * HD + k] = lo;
    } else if (idx < convTotal + 2 * HD * HD) {
        int r = idx - convTotal;
        int k = r >> 7, nn = r & 127;
        float v = w1[(size_t)k * HD + nn];
        __nv_bfloat16 hi = __float2bfloat16(v);
        __nv_bfloat16 lo = __float2bfloat16(v - __bfloat162float(hi));
        g_wt1[(size_t)nn * 256 + k] = hi;
        g_wt1[(size_t)HD * 2 * HD + nn * 256 + k] = lo;
    }
}

// ---------------- conv GEMM: cp.async double-buffered HMMA ----------------
// D = agg@Wr + x@Wo via bf16 splits: 6 stages x 2 k-chunks = 12 steps of K=64.
__device__ __forceinline__ void conv_issue(
    int step, int row0, int n, uint32_t sm, int t,
    const char* Ah0, const char* Al0, const char* Ah1, const char* Al1,
    const char* Wrh, const char* Wrl, const char* Woh, const char* Wol) {
    int stage = step >> 1, kc = step & 1;
    const char* As;
    const char* Bs;
    switch (stage) {
        case 0: As = Ah0; Bs = Wrh; break;
        case 1: As = Al0; Bs = Wrh; break;
        case 2: As = Ah0; Bs = Wrl; break;
        case 3: As = Ah1; Bs = Woh; break;
        case 4: As = Al1; Bs = Woh; break;
        default: As = Ah1; Bs = Wol; break;
    }
    uint32_t buf = sm + (step & 1) * BUF;
#pragma unroll
    for (int p = 0; p < 4; p++) {
        int idx = p * 256 + t;
        int r = idx >> 3, u = idx & 7;
        int gr = row0 + r;
        cp16(buf + r * PITCH + u * 16,
             As + (size_t)gr * 256 + kc * 128 + u * 16, (gr < n) ? 16 : 0);
        cp16(buf + TILE + r * PITCH + u * 16,
             Bs + (size_t)r * 256 + kc * 128 + u * 16, 16);
    }
}

__global__ void __launch_bounds__(256, 2) conv_mma(
    const char* __restrict__ Ah0, const char* __restrict__ Al0,
    const char* __restrict__ Ah1, const char* __restrict__ Al1,
    const char* __restrict__ Wrh, const char* __restrict__ Wrl,
    const char* __restrict__ Woh, const char* __restrict__ Wol,
    const float* __restrict__ bias, float* __restrict__ Hout,
    float* __restrict__ stats, int n) {
    extern __shared__ __align__(16) char smp[];
    uint32_t sm = smem_u32(smp);
    int t = threadIdx.x, wid = t >> 5, lane = t & 31;
    int row0 = blockIdx.x * 128;
    int mbase = (wid & 1) * 64, nbase = (wid >> 1) * 32;

    float c[4][4][4];
#pragma unroll
    for (int i = 0; i < 4; i++)
#pragma unroll
        for (int j = 0; j < 4; j++)
#pragma unroll
            for (int q = 0; q < 4; q++) c[i][j][q] = 0.f;

    int sub = lane >> 3, r8 = lane & 7;
    uint32_t laneA = (uint32_t)((mbase + r8 + (sub & 1) * 8) * PITCH + (sub >> 1) * 16);
    uint32_t laneB = (uint32_t)((nbase + (sub >> 1) * 8 + r8) * PITCH + (sub & 1) * 16);

    conv_issue(0, row0, n, sm, t, Ah0, Al0, Ah1, Al1, Wrh, Wrl, Woh, Wol);
    cp_commit();
#pragma unroll
    for (int s = 0; s < 12; s++) {
        if (s < 11) {
            conv_issue(s + 1, row0, n, sm, t, Ah0, Al0, Ah1, Al1, Wrh, Wrl, Woh, Wol);
            cp_commit();
            asm volatile("cp.async.wait_group 1;" ::: "memory");
        } else {
            asm volatile("cp.async.wait_group 0;" ::: "memory");
        }
        __syncthreads();
        uint32_t Ab = sm + (s & 1) * BUF + laneA;
        uint32_t Bb = sm + (s & 1) * BUF + TILE + laneB;
#pragma unroll
        for (int ks = 0; ks < 4; ks++) {
            uint32_t a[4][4], b[8];
#pragma unroll
            for (int mt = 0; mt < 4; mt++) ldmx4(a[mt], Ab + mt * (16 * PITCH) + ks * 32);
#pragma unroll
            for (int bp = 0; bp < 2; bp++) ldmx4(b + bp * 4, Bb + bp * (16 * PITCH) + ks * 32);
#pragma unroll
            for (int mt = 0; mt < 4; mt++)
#pragma unroll
                for (int nt = 0; nt < 4; nt++) mma_bf16(c[mt][nt], a[mt], b + nt * 2);
        }
        __syncthreads();
    }

    // Epilogue: +bias, gelu, store, fused BN stats
    if (t < 128) {
        *(float*)(smp + STATS_OFF + t * 4) = 0.f;
        *(float*)(smp + STATS_OFF + 512 + t * 4) = 0.f;
    }
    __syncthreads();
    int g = lane >> 2, tq = lane & 3;
    float bv[8];
#pragma unroll
    for (int nt = 0; nt < 4; nt++) {
        bv[nt * 2 + 0] = __ldg(&bias[nbase + nt * 8 + tq * 2 + 0]);
        bv[nt * 2 + 1] = __ldg(&bias[nbase + nt * 8 + tq * 2 + 1]);
    }
    float colsum[8], colsq[8];
#pragma unroll
    for (int j = 0; j < 8; j++) { colsum[j] = 0.f; colsq[j] = 0.f; }
#pragma unroll
    for (int mt = 0; mt < 4; mt++) {
        int gr0 = row0 + mbase + mt * 16 + g, gr1 = gr0 + 8;
#pragma unroll
        for (int nt = 0; nt < 4; nt++) {
            int cb = nbase + nt * 8 + tq * 2;
            if (gr0 < n) {
                float o0 = gelu_exact(c[mt][nt][0] + bv[nt * 2]);
                float o1 = gelu_exact(c[mt][nt][1] + bv[nt * 2 + 1]);
                float2 w2v = make_float2(o0, o1);
                *(float2*)(Hout + (size_t)gr0 * HD + cb) = w2v;
                colsum[nt * 2] += o0; colsq[nt * 2] += o0 * o0;
                colsum[nt * 2 + 1] += o1; colsq[nt * 2 + 1] += o1 * o1;
            }
            if (gr1 < n) {
                float o2 = gelu_exact(c[mt][nt][2] + bv[nt * 2]);
                float o3 = gelu_exact(c[mt][nt][3] + bv[nt * 2 + 1]);
                float2 w2v = make_float2(o2, o3);
                *(float2*)(Hout + (size_t)gr1 * HD + cb) = w2v;
                colsum[nt * 2] += o2; colsq[nt * 2] += o2 * o2;
                colsum[nt * 2 + 1] += o3; colsq[nt * 2 + 1] += o3 * o3;
            }
        }
    }
#pragma unroll
    for (int j = 0; j < 8; j++) {
        float v = colsum[j], w = colsq[j];
        v += __shfl_down_sync(0xFFFFFFFF, v, 16); w += __shfl_down_sync(0xFFFFFFFF, w, 16);
        v += __shfl_down_sync(0xFFFFFFFF, v, 8);  w += __shfl_down_sync(0xFFFFFFFF, w, 8);
        v += __shfl_down_sync(0xFFFFFFFF, v, 4);  w += __shfl_down_sync(0xFFFFFFFF, w, 4);
        if (lane < 4) {
            int cb = nbase + (j >> 1) * 8 + lane * 2 + (j & 1);
            atomicAdd((float*)(smp + STATS_OFF + cb * 4), v);
            atomicAdd((float*)(smp + STATS_OFF + 512 + cb * 4), w);
        }
    }
    __syncthreads();
    if (t < 128) {
        atomicAdd(&stats[t], *(float*)(smp + STATS_OFF + t * 4));
        atomicAdd(&stats[HD + t], *(float*)(smp + STATS_OFF + 512 + t * 4));
    }
}

// ---------------- BN normalize + emit split bf16 ----------------
__global__ void bn_kernel(const float4* __restrict__ h4, const float* __restrict__ stats,
                          const float* __restrict__ g, const float* __restrict__ b,
                          float4* __restrict__ out4, uint2* __restrict__ xhi,
                          uint2* __restrict__ xlo, int n) {
    int i = blockIdx.x * blockDim.x + threadIdx.x;
    int total = n * 32;
    if (i >= total) return;
    int c4 = i & 31;
    float invN = 1.0f / (float)n;
    float4 s = ((const float4*)stats)[c4];
    float4 q = ((const float4*)stats)[32 + c4];
    float4 gg = ((const float4*)g)[c4];
    float4 bb = ((const float4*)b)[c4];
    float m0 = s.x * invN, m1 = s.y * invN, m2 = s.z * invN, m3 = s.w * invN;
    float sc0 = rsqrtf(fmaxf(q.x * invN - m0 * m0, 0.f) + 1e-5f) * gg.x;
    float sc1 = rsqrtf(fmaxf(q.y * invN - m1 * m1, 0.f) + 1e-5f) * gg.y;
    float sc2 = rsqrtf(fmaxf(q.z * invN - m2 * m2, 0.f) + 1e-5f) * gg.z;
    float sc3 = rsqrtf(fmaxf(q.w * invN - m3 * m3, 0.f) + 1e-5f) * gg.w;
    float4 h = h4[i];
    float4 o;
    o.x = (h.x - m0) * sc0 + bb.x;
    o.y = (h.y - m1) * sc1 + bb.y;
    o.z = (h.z - m2) * sc2 + bb.z;
    o.w = (h.w - m3) * sc3 + bb.w;
    out4[i] = o;
    uint32_t h0, l0, h1, l1;
    split2(o.x, o.y, h0, l0);
    split2(o.z, o.w, h1, l1);
    xhi[i] = make_uint2(h0, h1);
    xlo[i] = make_uint2(l0, l1);
}

// ---------------- edge MLP (HMMA, gathers pre-split bf16) ----------------
__global__ void __launch_bounds__(256, 2) mlp_mma(
    const char* __restrict__ Xhi, const char* __restrict__ Xlo,
    const int* __restrict__ eli,
    const __nv_bfloat16* __restrict__ W1h, const __nv_bfloat16* __restrict__ W1l,
    const float* __restrict__ B1, const float* __restrict__ W2,
    const float* __restrict__ B2, float* __restrict__ out, int EQ) {
    extern __shared__ __align__(16) char smp[];
    uint32_t sm = smem_u32(smp);
    int t = threadIdx.x, wid = t >> 5, lane = t & 31;
    int row0 = blockIdx.x * 128;
    int mbase = (wid & 1) * 64, nbase = (wid >> 1) * 32;

    if (t < HD) {
        *(float*)(smp + t * 4) = B1[t];
        *(float*)(smp + 512 + t * 4) = W2[t];
        *(float*)(smp + 1024 + t * 4) = 0.f;
        int gr = row0 + t;
        int e = (gr < EQ) ? gr : 0;
        *(int*)(smp + 1536 + t * 4) = eli[e];
        *(int*)(smp + 2048 + t * 4) = eli[EQ + e];
    }

    float c[4][4][4];
#pragma unroll
    for (int i = 0; i < 4; i++)
#pragma unroll
        for (int j = 0; j < 4; j++)
#pragma unroll
            for (int q = 0; q < 4; q++) c[i][j][q] = 0.f;

    int sub = lane >> 3, r8 = lane & 7;
    uint32_t laneA = (uint32_t)((mbase + r8 + (sub & 1) * 8) * PITCH + (sub >> 1) * 16);
    uint32_t laneB = (uint32_t)((nbase + (sub >> 1) * 8 + r8) * PITCH + (sub & 1) * 16);

    for (int ch = 0; ch < 4; ch++) {
        int idxOff = (ch < 2) ? 1536 : 2048;
        int kc = ch & 1;
        __syncthreads();
#pragma unroll
        for (int p = 0; p < 4; p++) {
            int idx = p * 256 + t;
            int r = idx >> 3, u = idx & 7;
            int node = *(const int*)(smp + idxOff + r * 4);
            uint4 vh = *(const uint4*)(Xhi + (size_t)node * 256 + kc * 128 + u * 16);
            uint4 vl = *(const uint4*)(Xlo + (size_t)node * 256 + kc * 128 + u * 16);
            *(uint4*)(smp + MLP_A + r * PITCH + u * 16) = vh;
            *(uint4*)(smp + MLP_A + TILE + r * PITCH + u * 16) = vl;
        }
#pragma unroll
        for (int p = 0; p < 4; p++) {
            int lin = p * 256 + t;
            int nn = lin >> 3, q = lin & 7;
            uint32_t off = (uint32_t)(nn * PITCH + q * 16);
            *(uint4*)(smp + MLP_A + 2 * TILE + off) =
                *(const uint4*)(W1h + (size_t)nn * 256 + ch * 64 + q * 8);
            *(uint4*)(smp + MLP_A + 3 * TILE + off) =
                *(const uint4*)(W1l + (size_t)nn * 256 + ch * 64 + q * 8);
        }
        __syncthreads();
#pragma unroll
        for (int ps = 0; ps < 3; ps++) {
            uint32_t Ab = sm + MLP_A + ((ps == 1) ? TILE : 0) + laneA;
            uint32_t Bb = sm + MLP_A + 2 * TILE + ((ps == 2) ? TILE : 0) + laneB;
#pragma unroll
            for (int ks = 0; ks < 4; ks++) {
                uint32_t a[4][4], b[8];
#pragma unroll
                for (int mt = 0; mt < 4; mt++) ldmx4(a[mt], Ab + mt * (16 * PITCH) + ks * 32);
#pragma unroll
                for (int bp = 0; bp < 2; bp++) ldmx4(b + bp * 4, Bb + bp * (16 * PITCH) + ks * 32);
#pragma unroll
                for (int mt = 0; mt < 4; mt++)
#pragma unroll
                    for (int nt = 0; nt < 4; nt++) mma_bf16(c[mt][nt], a[mt], b + nt * 2);
            }
        }
    }

    int g = lane >> 2, tq = lane & 3;
#pragma unroll
    for (int mt = 0; mt < 4; mt++) {
        float p0 = 0.f, p1 = 0.f;
#pragma unroll
        for (int nt = 0; nt < 4; nt++) {
            int cb = nbase + nt * 8 + tq * 2;
            float2 bvv = *(float2*)(smp + cb * 4);
            float2 wv = *(float2*)(smp + 512 + cb * 4);
            p0 += gelu_exact(c[mt][nt][0] + bvv.x) * wv.x
                + gelu_exact(c[mt][nt][1] + bvv.y) * wv.y;
            p1 += gelu_exact(c[mt][nt][2] + bvv.x) * wv.x
                + gelu_exact(c[mt][nt][3] + bvv.y) * wv.y;
        }
        p0 += __shfl_xor_sync(0xFFFFFFFF, p0, 1);
        p0 += __shfl_xor_sync(0xFFFFFFFF, p0, 2);
        p1 += __shfl_xor_sync(0xFFFFFFFF, p1, 1);
        p1 += __shfl_xor_sync(0xFFFFFFFF, p1, 2);
        if (tq == 0) {
            int lr = mbase + mt * 16 + g;
            atomicAdd((float*)(smp + 1024 + lr * 4), p0);
            atomicAdd((float*)(smp + 1024 + (lr + 8) * 4), p1);
        }
    }
    __syncthreads();
    if (t < 128) {
        int gr = row0 + t;
        if (gr < EQ) {
            float z = *(float*)(smp + 1024 + t * 4) + B2[0];
            out[gr] = 1.0f / (1.0f + expf(-z));
        }
    }
}

// ---------------------------------------------------------------------------
extern "C" void kernel_launch(void* const* d_in, const int* in_sizes, int n_in,
                              void* d_out, int out_size) {
    const float* x      = (const float*)d_in[0];
    const int*   ei     = (const int*)d_in[1];
    const float* ea     = (const float*)d_in[2];
    const int*   eli    = (const int*)d_in[3];
    const float* rel_w  = (const float*)d_in[4];
    const float* rel_b  = (const float*)d_in[5];
    const float* root_w = (const float*)d_in[6];
    const float* bn_g   = (const float*)d_in[7];
    const float* bn_b   = (const float*)d_in[8];
    const float* w1     = (const float*)d_in[9];
    const float* b1     = (const float*)d_in[10];
    const float* w2     = (const float*)d_in[11];
    const float* b2     = (const float*)d_in[12];

    int N  = in_sizes[0] / HD;
    int E  = in_sizes[1] / 2;
    int EQ = in_sizes[3] / 2;
    int NC = in_sizes[4] / (HD * HD);

    float *hbuf, *xbuf, *stats;
    __nv_bfloat16 *ahi, *alo, *xhi, *xlo, *wtc, *wt1;
    int *deg, *tmp, *part, *rowptr, *cursor, *csrc;
    float *csw;
    cudaGetSymbolAddress((void**)&hbuf,   g_h);
    cudaGetSymbolAddress((void**)&xbuf,   g_x);
    cudaGetSymbolAddress((void**)&stats,  g_stats);
    cudaGetSymbolAddress((void**)&ahi,    g_agg_hi);
    cudaGetSymbolAddress((void**)&alo,    g_agg_lo);
    cudaGetSymbolAddress((void**)&xhi,    g_xhi);
    cudaGetSymbolAddress((void**)&xlo,    g_xlo);
    cudaGetSymbolAddress((void**)&deg,    g_deg);
    cudaGetSymbolAddress((void**)&tmp,    g_tmp);
    cudaGetSymbolAddress((void**)&part,   g_part);
    cudaGetSymbolAddress((void**)&rowptr, g_rowptr);
    cudaGetSymbolAddress((void**)&cursor, g_cursor);
    cudaGetSymbolAddress((void**)&csrc,   g_csrc);
    cudaGetSymbolAddress((void**)&csw,    g_csw);
    cudaGetSymbolAddress((void**)&wtc,    g_wtc);
    cudaGetSymbolAddress((void**)&wt1,    g_wt1);

    cudaFuncSetAttribute(conv_mma, cudaFuncAttributeMaxDynamicSharedMemorySize, CONV_SMEM);
    cudaFuncSetAttribute(mlp_mma,  cudaFuncAttributeMaxDynamicSharedMemorySize, MLP_SMEM);

    int n32 = N * 32;
    int pb = (NC * 2 * HD * HD + 2 * HD * HD + 255) / 256;
    int NB = (N + 1023) / 1024;
    int gb = (N + 127) / 128;
    int mb = (EQ + 127) / 128;

    prep_w<<<pb, 256>>>(rel_w, root_w, w1, NC);
    split_x<<<(n32 + 255) / 256, 256>>>((const float4*)x, (uint2*)xhi, (uint2*)xlo, n32);
    zero_deg<<<(N + 255) / 256, 256>>>(deg, N);
    hist_kernel<<<(E + 255) / 256, 256>>>(ei, deg, E);
    scan1<<<NB, 256>>>(deg, tmp, part, N);
    scan2<<<1, 32>>>(part, NB);
    scan3<<<(N + 256) / 256, 256>>>(tmp, part, rowptr, cursor, N, E);
    fill_csr<<<(E + 255) / 256, 256>>>(ei, ea, cursor, csrc, csw, E);

    const float* xcur = x;
    for (int l = 0; l < NC; l++) {
        agg_kernel<<<(N + 7) / 8, 256>>>((const float4*)xcur, rowptr, csrc, csw,
                                         (uint2*)ahi, (uint2*)alo, stats, N);
        size_t wb = (size_t)(l * 2) * 2 * HD * HD;
        conv_mma<<<gb, 256, CONV_SMEM>>>(
            (const char*)ahi, (const char*)alo, (const char*)xhi, (const char*)xlo,
            (const char*)(wtc + wb), (const char*)(wtc + wb + HD * HD),
            (const char*)(wtc + wb + 2 * HD * HD), (const char*)(wtc + wb + 3 * HD * HD),
            rel_b + (size_t)l * HD, hbuf, stats, N);
        bn_kernel<<<(n32 + 255) / 256, 256>>>((const float4*)hbuf, stats,
                                              bn_g + (size_t)l * HD, bn_b + (size_t)l * HD,
                                              (float4*)xbuf, (uint2*)xhi, (uint2*)xlo, N);
        xcur = xbuf;
    }
    mlp_mma<<<mb, 256, MLP_SMEM>>>((const char*)xhi, (const char*)xlo, eli,
                                   wt1, wt1 + (size_t)HD * 2 * HD,
                                   b1, w2, b2, (float*)d_out, EQ);
}

// round 6
// speedup vs baseline: 2.0432x; 1.0073x over previous
#include <cuda_runtime.h>
#include <cuda_bf16.h>
#include <math.h>
#include <stdint.h>

#define HD 128
#define MAXN 100000
#define MAXE 600000
#define NCMAX 4

// ---------------- scratch globals ----------------
__device__ float g_h[MAXN * HD];
__device__ float g_stats[2 * HD];
__device__ __nv_bfloat16 g_agg_hi[MAXN * HD];
__device__ __nv_bfloat16 g_agg_lo[MAXN * HD];
__device__ __nv_bfloat16 g_xhi[MAXN * HD];
__device__ __nv_bfloat16 g_xlo[MAXN * HD];
__device__ int g_deg[MAXN];
__device__ int g_tmp[MAXN + 1024];
__device__ int g_part[128];
__device__ int g_rowptr[MAXN + 1];
__device__ int g_cursor[MAXN];
__device__ int g_csrc[MAXE];
__device__ float g_csw[MAXE];
__device__ __nv_bfloat16 g_wtc[NCMAX * 2 * 2 * HD * HD];
__device__ __nv_bfloat16 g_wt1[2 * HD * 2 * HD];

// ---------------- tiling constants ----------------
#define PITCH 176
#define TILE (128 * PITCH)      // 22528
#define BUF (2 * TILE)          // 45056: A tile + B tile
#define STATS_OFF (2 * BUF)     // 90112
#define CONV_SMEM (STATS_OFF + 1024)  // 91136
#define MLP_A 2560
#define MLP_SMEM (MLP_A + 4 * TILE)   // 92672

__device__ __forceinline__ float gelu_exact(float v) {
    return 0.5f * v * (1.0f + erff(v * 0.70710678118654752440f));
}
__device__ __forceinline__ uint32_t smem_u32(const void* p) {
    uint32_t a;
    asm("{ .reg .u64 t; cvta.to.shared.u64 t, %1; cvt.u32.u64 %0, t; }" : "=r"(a) : "l"(p));
    return a;
}
__device__ __forceinline__ uint32_t bfbits(__nv_bfloat16 h) {
    return (uint32_t)__bfloat16_as_ushort(h);
}
__device__ __forceinline__ void split2(float x, float y, uint32_t& hi, uint32_t& lo) {
    __nv_bfloat16 hx = __float2bfloat16(x), hy = __float2bfloat16(y);
    __nv_bfloat16 lx = __float2bfloat16(x - __bfloat162float(hx));
    __nv_bfloat16 ly = __float2bfloat16(y - __bfloat162float(hy));
    hi = bfbits(hx) | (bfbits(hy) << 16);
    lo = bfbits(lx) | (bfbits(ly) << 16);
}
// unpack packed bf16x2 pair (hi bits + lo bits) into reconstructed float2
__device__ __forceinline__ float2 recon2(uint32_t hb, uint32_t lb) {
    float2 h = __bfloat1622float2(*(__nv_bfloat162*)&hb);
    float2 l = __bfloat1622float2(*(__nv_bfloat162*)&lb);
    return make_float2(h.x + l.x, h.y + l.y);
}
__device__ __forceinline__ void ldmx4(uint32_t* r, uint32_t addr) {
    asm volatile("ldmatrix.sync.aligned.m8n8.x4.shared.b16 {%0,%1,%2,%3}, [%4];"
                 : "=r"(r[0]), "=r"(r[1]), "=r"(r[2]), "=r"(r[3]) : "r"(addr));
}
__device__ __forceinline__ void mma_bf16(float* c, const uint32_t* a, const uint32_t* b) {
    asm volatile(
        "mma.sync.aligned.m16n8k16.row.col.f32.bf16.bf16.f32 "
        "{%0,%1,%2,%3},{%4,%5,%6,%7},{%8,%9},{%0,%1,%2,%3};"
        : "+f"(c[0]), "+f"(c[1]), "+f"(c[2]), "+f"(c[3])
        : "r"(a[0]), "r"(a[1]), "r"(a[2]), "r"(a[3]), "r"(b[0]), "r"(b[1]));
}
__device__ __forceinline__ void cp16(uint32_t dst, const void* src, int sz) {
    asm volatile("cp.async.cg.shared.global [%0], [%1], 16, %2;"
                 :: "r"(dst), "l"(src), "r"(sz) : "memory");
}
__device__ __forceinline__ void cp_commit() {
    asm volatile("cp.async.commit_group;" ::: "memory");
}

// ---------------- CSR build ----------------
__global__ void hist_kernel(const int* __restrict__ ei, int* __restrict__ deg, int E) {
    int e = blockIdx.x * 256 + threadIdx.x;
    if (e < E) atomicAdd(&deg[ei[E + e]], 1);
}
__global__ void scan1(const int* __restrict__ deg, int* __restrict__ tmp,
                      int* __restrict__ part, int n) {
    __shared__ int warpsum[8];
    int b = blockIdx.x, t = threadIdx.x;
    int base = b * 1024 + t * 4;
    int v0 = (base + 0 < n) ? deg[base + 0] : 0;
    int v1 = (base + 1 < n) ? deg[base + 1] : 0;
    int v2 = (base + 2 < n) ? deg[base + 2] : 0;
    int v3 = (base + 3 < n) ? deg[base + 3] : 0;
    int s0 = v0, s1 = s0 + v1, s2 = s1 + v2, s3 = s2 + v3;
    int tot = s3;
#pragma unroll
    for (int d = 1; d < 32; d <<= 1) {
        int u = __shfl_up_sync(0xFFFFFFFF, tot, d);
        if ((t & 31) >= d) tot += u;
    }
    if ((t & 31) == 31) warpsum[t >> 5] = tot;
    __syncthreads();
    if (t == 0) {
        int r = 0;
#pragma unroll
        for (int i = 0; i < 8; i++) { int x = warpsum[i]; warpsum[i] = r; r += x; }
        part[b] = r;
    }
    __syncthreads();
    int excl = warpsum[t >> 5] + (tot - s3);
    if (base + 0 <= n) tmp[base + 0] = excl;
    if (base + 1 <= n) tmp[base + 1] = excl + s0;
    if (base + 2 <= n) tmp[base + 2] = excl + s1;
    if (base + 3 <= n) tmp[base + 3] = excl + s2;
}
__global__ void scan2(int* part, int nb) {
    if (threadIdx.x == 0) {
        int r = 0;
        for (int i = 0; i < nb; i++) { int x = part[i]; part[i] = r; r += x; }
    }
}
__global__ void scan3(const int* __restrict__ tmp, const int* __restrict__ part,
                      int* __restrict__ rowptr, int* __restrict__ cursor, int n, int E) {
    int i = blockIdx.x * 256 + threadIdx.x;
    if (i < n) {
        int v = tmp[i] + part[i >> 10];
        rowptr[i] = v;
        cursor[i] = v;
    }
    if (i == n) rowptr[n] = E;
}
__global__ void fill_csr(const int* __restrict__ ei, const float* __restrict__ ea,
                         int* __restrict__ cursor, int* __restrict__ csrc,
                         float* __restrict__ csw, int E) {
    int e = blockIdx.x * 256 + threadIdx.x;
    if (e >= E) return;
    int d = ei[E + e];
    int pos = atomicAdd(&cursor[d], 1);
    csrc[pos] = ei[e];
    csw[pos] = ea[e];
}

// ---------------- split x + zero deg ----------------
__global__ void split_x(const float4* __restrict__ x4, uint2* __restrict__ xhi,
                        uint2* __restrict__ xlo, int* __restrict__ deg, int n32, int n) {
    int i = blockIdx.x * 256 + threadIdx.x;
    if (i < n) deg[i] = 0;
    if (i >= n32) return;
    float4 v = x4[i];
    uint32_t h0, l0, h1, l1;
    split2(v.x, v.y, h0, l0);
    split2(v.z, v.w, h1, l1);
    xhi[i] = make_uint2(h0, h1);
    xlo[i] = make_uint2(l0, l1);
}

// ---------------- CSR aggregation: warp per node, bf16-split gather ----------------
__global__ void agg_kernel(const uint2* __restrict__ xhi, const uint2* __restrict__ xlo,
                           const int* __restrict__ rowptr,
                           const int* __restrict__ csrc, const float* __restrict__ csw,
                           uint2* __restrict__ ahi, uint2* __restrict__ alo,
                           float* __restrict__ stats, int nn) {
    if (blockIdx.x == 0 && threadIdx.x < 2 * HD) stats[threadIdx.x] = 0.f;
    int node = (blockIdx.x * blockDim.x + threadIdx.x) >> 5;
    int lane = threadIdx.x & 31;
    if (node >= nn) return;
    int beg = rowptr[node], end = rowptr[node + 1];
    float4 acc = make_float4(0.f, 0.f, 0.f, 0.f);
    for (int e = beg; e < end; e++) {
        int s = __ldg(&csrc[e]);
        float w = __ldg(&csw[e]);
        uint2 vh = __ldg(&xhi[(size_t)s * 32 + lane]);
        uint2 vl = __ldg(&xlo[(size_t)s * 32 + lane]);
        float2 v01 = recon2(vh.x, vl.x);
        float2 v23 = recon2(vh.y, vl.y);
        acc.x += v01.x * w; acc.y += v01.y * w;
        acc.z += v23.x * w; acc.w += v23.y * w;
    }
    uint32_t h0, l0, h1, l1;
    split2(acc.x, acc.y, h0, l0);
    split2(acc.z, acc.w, h1, l1);
    ahi[(size_t)node * 32 + lane] = make_uint2(h0, h1);
    alo[(size_t)node * 32 + lane] = make_uint2(l0, l1);
}

// ---------------- weight prep (transpose + split) ----------------
__global__ void prep_w(const float* __restrict__ rel_w, const float* __restrict__ root_w,
                       const float* __restrict__ w1, int NC) {
    int idx = blockIdx.x * 256 + threadIdx.x;
    int convTotal = NC * 2 * HD * HD;
    if (idx < convTotal) {
        int l = idx / (2 * HD * HD);
        int rem = idx % (2 * HD * HD);
        int m = rem / (HD * HD);
        int r = rem % (HD * HD);
        int k = r >> 7, nn = r & 127;
        const float* W = m ? root_w : rel_w;
        float v = W[(size_t)l * HD * HD + k * HD + nn];
        __nv_bfloat16 hi = __float2bfloat16(v);
        __nv_bfloat16 lo = __float2bfloat16(v - __bfloat162float(hi));
        size_t base = ((size_t)(l * 2 + m) * 2) * HD * HD;
        g_wtc[base + nn * HD + k] = hi;
        g_wtc[base + HD * HD + nn * HD + k] = lo;
    } else if (idx < convTotal + 2 * HD * HD) {
        int r = idx - convTotal;
        int k = r >> 7, nn = r & 127;
        float v = w1[(size_t)k * HD + nn];
        __nv_bfloat16 hi = __float2bfloat16(v);
        __nv_bfloat16 lo = __float2bfloat16(v - __bfloat162float(hi));
        g_wt1[(size_t)nn * 256 + k] = hi;
        g_wt1[(size_t)HD * 2 * HD + nn * 256 + k] = lo;
    }
}

// ---------------- conv GEMM: cp.async double-buffered HMMA ----------------
__device__ __forceinline__ void conv_issue(
    int step, int row0, int n, uint32_t sm, int t,
    const char* Ah0, const char* Al0, const char* Ah1, const char* Al1,
    const char* Wrh, const char* Wrl, const char* Woh, const char* Wol) {
    int stage = step >> 1, kc = step & 1;
    const char* As;
    const char* Bs;
    switch (stage) {
        case 0: As = Ah0; Bs = Wrh; break;
        case 1: As = Al0; Bs = Wrh; break;
        case 2: As = Ah0; Bs = Wrl; break;
        case 3: As = Ah1; Bs = Woh; break;
        case 4: As = Al1; Bs = Woh; break;
        default: As = Ah1; Bs = Wol; break;
    }
    uint32_t buf = sm + (step & 1) * BUF;
#pragma unroll
    for (int p = 0; p < 4; p++) {
        int idx = p * 256 + t;
        int r = idx >> 3, u = idx & 7;
        int gr = row0 + r;
        cp16(buf + r * PITCH + u * 16,
             As + (size_t)gr * 256 + kc * 128 + u * 16, (gr < n) ? 16 : 0);
        cp16(buf + TILE + r * PITCH + u * 16,
             Bs + (size_t)r * 256 + kc * 128 + u * 16, 16);
    }
}

__global__ void __launch_bounds__(256, 2) conv_mma(
    const char* __restrict__ Ah0, const char* __restrict__ Al0,
    const char* __restrict__ Ah1, const char* __restrict__ Al1,
    const char* __restrict__ Wrh, const char* __restrict__ Wrl,
    const char* __restrict__ Woh, const char* __restrict__ Wol,
    const float* __restrict__ bias, float* __restrict__ Hout,
    float* __restrict__ stats, int n) {
    extern __shared__ __align__(16) char smp[];
    uint32_t sm = smem_u32(smp);
    int t = threadIdx.x, wid = t >> 5, lane = t & 31;
    int row0 = blockIdx.x * 128;
    int mbase = (wid & 1) * 64, nbase = (wid >> 1) * 32;

    float c[4][4][4];
#pragma unroll
    for (int i = 0; i < 4; i++)
#pragma unroll
        for (int j = 0; j < 4; j++)
#pragma unroll
            for (int q = 0; q < 4; q++) c[i][j][q] = 0.f;

    int sub = lane >> 3, r8 = lane & 7;
    uint32_t laneA = (uint32_t)((mbase + r8 + (sub & 1) * 8) * PITCH + (sub >> 1) * 16);
    uint32_t laneB = (uint32_t)((nbase + (sub >> 1) * 8 + r8) * PITCH + (sub & 1) * 16);

    conv_issue(0, row0, n, sm, t, Ah0, Al0, Ah1, Al1, Wrh, Wrl, Woh, Wol);
    cp_commit();
#pragma unroll
    for (int s = 0; s < 12; s++) {
        if (s < 11) {
            conv_issue(s + 1, row0, n, sm, t, Ah0, Al0, Ah1, Al1, Wrh, Wrl, Woh, Wol);
            cp_commit();
            asm volatile("cp.async.wait_group 1;" ::: "memory");
        } else {
            asm volatile("cp.async.wait_group 0;" ::: "memory");
        }
        __syncthreads();
        uint32_t Ab = sm + (s & 1) * BUF + laneA;
        uint32_t Bb = sm + (s & 1) * BUF + TILE + laneB;
#pragma unroll
        for (int ks = 0; ks < 4; ks++) {
            uint32_t a[4][4], b[8];
#pragma unroll
            for (int mt = 0; mt < 4; mt++) ldmx4(a[mt], Ab + mt * (16 * PITCH) + ks * 32);
#pragma unroll
            for (int bp = 0; bp < 2; bp++) ldmx4(b + bp * 4, Bb + bp * (16 * PITCH) + ks * 32);
#pragma unroll
            for (int mt = 0; mt < 4; mt++)
#pragma unroll
                for (int nt = 0; nt < 4; nt++) mma_bf16(c[mt][nt], a[mt], b + nt * 2);
        }
        __syncthreads();
    }

    // Epilogue: +bias, gelu, store, fused BN stats
    if (t < 128) {
        *(float*)(smp + STATS_OFF + t * 4) = 0.f;
        *(float*)(smp + STATS_OFF + 512 + t * 4) = 0.f;
    }
    __syncthreads();
    int g = lane >> 2, tq = lane & 3;
    float bv[8];
#pragma unroll
    for (int nt = 0; nt < 4; nt++) {
        bv[nt * 2 + 0] = __ldg(&bias[nbase + nt * 8 + tq * 2 + 0]);
        bv[nt * 2 + 1] = __ldg(&bias[nbase + nt * 8 + tq * 2 + 1]);
    }
    float colsum[8], colsq[8];
#pragma unroll
    for (int j = 0; j < 8; j++) { colsum[j] = 0.f; colsq[j] = 0.f; }
#pragma unroll
    for (int mt = 0; mt < 4; mt++) {
        int gr0 = row0 + mbase + mt * 16 + g, gr1 = gr0 + 8;
#pragma unroll
        for (int nt = 0; nt < 4; nt++) {
            int cb = nbase + nt * 8 + tq * 2;
            if (gr0 < n) {
                float o0 = gelu_exact(c[mt][nt][0] + bv[nt * 2]);
                float o1 = gelu_exact(c[mt][nt][1] + bv[nt * 2 + 1]);
                *(float2*)(Hout + (size_t)gr0 * HD + cb) = make_float2(o0, o1);
                colsum[nt * 2] += o0; colsq[nt * 2] += o0 * o0;
                colsum[nt * 2 + 1] += o1; colsq[nt * 2 + 1] += o1 * o1;
            }
            if (gr1 < n) {
                float o2 = gelu_exact(c[mt][nt][2] + bv[nt * 2]);
                float o3 = gelu_exact(c[mt][nt][3] + bv[nt * 2 + 1]);
                *(float2*)(Hout + (size_t)gr1 * HD + cb) = make_float2(o2, o3);
                colsum[nt * 2] += o2; colsq[nt * 2] += o2 * o2;
                colsum[nt * 2 + 1] += o3; colsq[nt * 2 + 1] += o3 * o3;
            }
        }
    }
#pragma unroll
    for (int j = 0; j < 8; j++) {
        float v = colsum[j], w = colsq[j];
        v += __shfl_down_sync(0xFFFFFFFF, v, 16); w += __shfl_down_sync(0xFFFFFFFF, w, 16);
        v += __shfl_down_sync(0xFFFFFFFF, v, 8);  w += __shfl_down_sync(0xFFFFFFFF, w, 8);
        v += __shfl_down_sync(0xFFFFFFFF, v, 4);  w += __shfl_down_sync(0xFFFFFFFF, w, 4);
        if (lane < 4) {
            int cb = nbase + (j >> 1) * 8 + lane * 2 + (j & 1);
            atomicAdd((float*)(smp + STATS_OFF + cb * 4), v);
            atomicAdd((float*)(smp + STATS_OFF + 512 + cb * 4), w);
        }
    }
    __syncthreads();
    if (t < 128) {
        atomicAdd(&stats[t], *(float*)(smp + STATS_OFF + t * 4));
        atomicAdd(&stats[HD + t], *(float*)(smp + STATS_OFF + 512 + t * 4));
    }
}

// ---------------- BN normalize -> emit split bf16 only ----------------
__global__ void bn_kernel(const float4* __restrict__ h4, const float* __restrict__ stats,
                          const float* __restrict__ g, const float* __restrict__ b,
                          uint2* __restrict__ xhi, uint2* __restrict__ xlo, int n) {
    int i = blockIdx.x * blockDim.x + threadIdx.x;
    int total = n * 32;
    if (i >= total) return;
    int c4 = i & 31;
    float invN = 1.0f / (float)n;
    float4 s = ((const float4*)stats)[c4];
    float4 q = ((const float4*)stats)[32 + c4];
    float4 gg = ((const float4*)g)[c4];
    float4 bb = ((const float4*)b)[c4];
    float m0 = s.x * invN, m1 = s.y * invN, m2 = s.z * invN, m3 = s.w * invN;
    float sc0 = rsqrtf(fmaxf(q.x * invN - m0 * m0, 0.f) + 1e-5f) * gg.x;
    float sc1 = rsqrtf(fmaxf(q.y * invN - m1 * m1, 0.f) + 1e-5f) * gg.y;
    float sc2 = rsqrtf(fmaxf(q.z * invN - m2 * m2, 0.f) + 1e-5f) * gg.z;
    float sc3 = rsqrtf(fmaxf(q.w * invN - m3 * m3, 0.f) + 1e-5f) * gg.w;
    float4 h = h4[i];
    float ox = (h.x - m0) * sc0 + bb.x;
    float oy = (h.y - m1) * sc1 + bb.y;
    float oz = (h.z - m2) * sc2 + bb.z;
    float ow = (h.w - m3) * sc3 + bb.w;
    uint32_t h0, l0, h1, l1;
    split2(ox, oy, h0, l0);
    split2(oz, ow, h1, l1);
    xhi[i] = make_uint2(h0, h1);
    xlo[i] = make_uint2(l0, l1);
}

// ---------------- edge MLP (HMMA, gathers pre-split bf16) ----------------
__global__ void __launch_bounds__(256, 2) mlp_mma(
    const char* __restrict__ Xhi, const char* __restrict__ Xlo,
    const int* __restrict__ eli,
    const __nv_bfloat16* __restrict__ W1h, const __nv_bfloat16* __restrict__ W1l,
    const float* __restrict__ B1, const float* __restrict__ W2,
    const float* __restrict__ B2, float* __restrict__ out, int EQ) {
    extern __shared__ __align__(16) char smp[];
    uint32_t sm = smem_u32(smp);
    int t = threadIdx.x, wid = t >> 5, lane = t & 31;
    int row0 = blockIdx.x * 128;
    int mbase = (wid & 1) * 64, nbase = (wid >> 1) * 32;

    if (t < HD) {
        *(float*)(smp + t * 4) = B1[t];
        *(float*)(smp + 512 + t * 4) = W2[t];
        *(float*)(smp + 1024 + t * 4) = 0.f;
        int gr = row0 + t;
        int e = (gr < EQ) ? gr : 0;
        *(int*)(smp + 1536 + t * 4) = eli[e];
        *(int*)(smp + 2048 + t * 4) = eli[EQ + e];
    }

    float c[4][4][4];
#pragma unroll
    for (int i = 0; i < 4; i++)
#pragma unroll
        for (int j = 0; j < 4; j++)
#pragma unroll
            for (int q = 0; q < 4; q++) c[i][j][q] = 0.f;

    int sub = lane >> 3, r8 = lane & 7;
    uint32_t laneA = (uint32_t)((mbase + r8 + (sub & 1) * 8) * PITCH + (sub >> 1) * 16);
    uint32_t laneB = (uint32_t)((nbase + (sub >> 1) * 8 + r8) * PITCH + (sub & 1) * 16);

    for (int ch = 0; ch < 4; ch++) {
        int idxOff = (ch < 2) ? 1536 : 2048;
        int kc = ch & 1;
        __syncthreads();
#pragma unroll
        for (int p = 0; p < 4; p++) {
            int idx = p * 256 + t;
            int r = idx >> 3, u = idx & 7;
            int node = *(const int*)(smp + idxOff + r * 4);
            uint4 vh = *(const uint4*)(Xhi + (size_t)node * 256 + kc * 128 + u * 16);
            uint4 vl = *(const uint4*)(Xlo + (size_t)node * 256 + kc * 128 + u * 16);
            *(uint4*)(smp + MLP_A + r * PITCH + u * 16) = vh;
            *(uint4*)(smp + MLP_A + TILE + r * PITCH + u * 16) = vl;
        }
#pragma unroll
        for (int p = 0; p < 4; p++) {
            int lin = p * 256 + t;
            int nn = lin >> 3, q = lin & 7;
            uint32_t off = (uint32_t)(nn * PITCH + q * 16);
            *(uint4*)(smp + MLP_A + 2 * TILE + off) =
                *(const uint4*)(W1h + (size_t)nn * 256 + ch * 64 + q * 8);
            *(uint4*)(smp + MLP_A + 3 * TILE + off) =
                *(const uint4*)(W1l + (size_t)nn * 256 + ch * 64 + q * 8);
        }
        __syncthreads();
#pragma unroll
        for (int ps = 0; ps < 3; ps++) {
            uint32_t Ab = sm + MLP_A + ((ps == 1) ? TILE : 0) + laneA;
            uint32_t Bb = sm + MLP_A + 2 * TILE + ((ps == 2) ? TILE : 0) + laneB;
#pragma unroll
            for (int ks = 0; ks < 4; ks++) {
                uint32_t a[4][4], b[8];
#pragma unroll
                for (int mt = 0; mt < 4; mt++) ldmx4(a[mt], Ab + mt * (16 * PITCH) + ks * 32);
#pragma unroll
                for (int bp = 0; bp < 2; bp++) ldmx4(b + bp * 4, Bb + bp * (16 * PITCH) + ks * 32);
#pragma unroll
                for (int mt = 0; mt < 4; mt++)
#pragma unroll
                    for (int nt = 0; nt < 4; nt++) mma_bf16(c[mt][nt], a[mt], b + nt * 2);
            }
        }
    }

    int g = lane >> 2, tq = lane & 3;
#pragma unroll
    for (int mt = 0; mt < 4; mt++) {
        float p0 = 0.f, p1 = 0.f;
#pragma unroll
        for (int nt = 0; nt < 4; nt++) {
            int cb = nbase + nt * 8 + tq * 2;
            float2 bvv = *(float2*)(smp + cb * 4);
            float2 wv = *(float2*)(smp + 512 + cb * 4);
            p0 += gelu_exact(c[mt][nt][0] + bvv.x) * wv.x
                + gelu_exact(c[mt][nt][1] + bvv.y) * wv.y;
            p1 += gelu_exact(c[mt][nt][2] + bvv.x) * wv.x
                + gelu_exact(c[mt][nt][3] + bvv.y) * wv.y;
        }
        p0 += __shfl_xor_sync(0xFFFFFFFF, p0, 1);
        p0 += __shfl_xor_sync(0xFFFFFFFF, p0, 2);
        p1 += __shfl_xor_sync(0xFFFFFFFF, p1, 1);
        p1 += __shfl_xor_sync(0xFFFFFFFF, p1, 2);
        if (tq == 0) {
            int lr = mbase + mt * 16 + g;
            atomicAdd((float*)(smp + 1024 + lr * 4), p0);
            atomicAdd((float*)(smp + 1024 + (lr + 8) * 4), p1);
        }
    }
    __syncthreads();
    if (t < 128) {
        int gr = row0 + t;
        if (gr < EQ) {
            float z = *(float*)(smp + 1024 + t * 4) + B2[0];
            out[gr] = 1.0f / (1.0f + expf(-z));
        }
    }
}

// ---------------------------------------------------------------------------
extern "C" void kernel_launch(void* const* d_in, const int* in_sizes, int n_in,
                              void* d_out, int out_size) {
    const float* x      = (const float*)d_in[0];
    const int*   ei     = (const int*)d_in[1];
    const float* ea     = (const float*)d_in[2];
    const int*   eli    = (const int*)d_in[3];
    const float* rel_w  = (const float*)d_in[4];
    const float* rel_b  = (const float*)d_in[5];
    const float* root_w = (const float*)d_in[6];
    const float* bn_g   = (const float*)d_in[7];
    const float* bn_b   = (const float*)d_in[8];
    const float* w1     = (const float*)d_in[9];
    const float* b1     = (const float*)d_in[10];
    const float* w2     = (const float*)d_in[11];
    const float* b2     = (const float*)d_in[12];

    int N  = in_sizes[0] / HD;
    int E  = in_sizes[1] / 2;
    int EQ = in_sizes[3] / 2;
    int NC = in_sizes[4] / (HD * HD);

    float *hbuf, *stats;
    __nv_bfloat16 *ahi, *alo, *xhi, *xlo, *wtc, *wt1;
    int *deg, *tmp, *part, *rowptr, *cursor, *csrc;
    float *csw;
    cudaGetSymbolAddress((void**)&hbuf,   g_h);
    cudaGetSymbolAddress((void**)&stats,  g_stats);
    cudaGetSymbolAddress((void**)&ahi,    g_agg_hi);
    cudaGetSymbolAddress((void**)&alo,    g_agg_lo);
    cudaGetSymbolAddress((void**)&xhi,    g_xhi);
    cudaGetSymbolAddress((void**)&xlo,    g_xlo);
    cudaGetSymbolAddress((void**)&deg,    g_deg);
    cudaGetSymbolAddress((void**)&tmp,    g_tmp);
    cudaGetSymbolAddress((void**)&part,   g_part);
    cudaGetSymbolAddress((void**)&rowptr, g_rowptr);
    cudaGetSymbolAddress((void**)&cursor, g_cursor);
    cudaGetSymbolAddress((void**)&csrc,   g_csrc);
    cudaGetSymbolAddress((void**)&csw,    g_csw);
    cudaGetSymbolAddress((void**)&wtc,    g_wtc);
    cudaGetSymbolAddress((void**)&wt1,    g_wt1);

    cudaFuncSetAttribute(conv_mma, cudaFuncAttributeMaxDynamicSharedMemorySize, CONV_SMEM);
    cudaFuncSetAttribute(mlp_mma,  cudaFuncAttributeMaxDynamicSharedMemorySize, MLP_SMEM);

    int n32 = N * 32;
    int pb = (NC * 2 * HD * HD + 2 * HD * HD + 255) / 256;
    int NB = (N + 1023) / 1024;
    int gb = (N + 127) / 128;
    int mb = (EQ + 127) / 128;

    prep_w<<<pb, 256>>>(rel_w, root_w, w1, NC);
    split_x<<<(n32 + 255) / 256, 256>>>((const float4*)x, (uint2*)xhi, (uint2*)xlo,
                                        deg, n32, N);
    hist_kernel<<<(E + 255) / 256, 256>>>(ei, deg, E);
    scan1<<<NB, 256>>>(deg, tmp, part, N);
    scan2<<<1, 32>>>(part, NB);
    scan3<<<(N + 256) / 256, 256>>>(tmp, part, rowptr, cursor, N, E);
    fill_csr<<<(E + 255) / 256, 256>>>(ei, ea, cursor, csrc, csw, E);

    for (int l = 0; l < NC; l++) {
        agg_kernel<<<(N + 7) / 8, 256>>>((const uint2*)xhi, (const uint2*)xlo,
                                         rowptr, csrc, csw,
                                         (uint2*)ahi, (uint2*)alo, stats, N);
        size_t wb = (size_t)(l * 2) * 2 * HD * HD;
        conv_mma<<<gb, 256, CONV_SMEM>>>(
            (const char*)ahi, (const char*)alo, (const char*)xhi, (const char*)xlo,
            (const char*)(wtc + wb), (const char*)(wtc + wb + HD * HD),
            (const char*)(wtc + wb + 2 * HD * HD), (const char*)(wtc + wb + 3 * HD * HD),
            rel_b + (size_t)l * HD, hbuf, stats, N);
        bn_kernel<<<(n32 + 255) / 256, 256>>>((const float4*)hbuf, stats,
                                              bn_g + (size_t)l * HD, bn_b + (size_t)l * HD,
                                              (uint2*)xhi, (uint2*)xlo, N);
    }
    mlp_mma<<<mb, 256, MLP_SMEM>>>((const char*)xhi, (const char*)xlo, eli,
                                   wt1, wt1 + (size_t)HD * 2 * HD,
                                   b1, w2, b2, (float*)d_out, EQ);
}

// round 7
// speedup vs baseline: 2.1755x; 1.0648x over previous
#include <cuda_runtime.h>
#include <cuda_bf16.h>
#include <math.h>
#include <stdint.h>

#define HD 128
#define MAXN 100000
#define MAXE 600000
#define NCMAX 4

// ---------------- scratch globals ----------------
__device__ float g_h[MAXN * HD];
__device__ float g_stats[2 * HD];
__device__ __nv_bfloat16 g_agg_hi[MAXN * HD];
__device__ __nv_bfloat16 g_agg_lo[MAXN * HD];
__device__ __nv_bfloat16 g_xhi[MAXN * HD];
__device__ __nv_bfloat16 g_xlo[MAXN * HD];
__device__ int g_deg[MAXN];
__device__ int g_tmp[MAXN + 1024];
__device__ int g_part[128];
__device__ int g_rowptr[MAXN + 1];
__device__ int g_cursor[MAXN];
__device__ int g_csrc[MAXE];
__device__ float g_csw[MAXE];
__device__ __nv_bfloat16 g_wtc[NCMAX * 2 * 2 * HD * HD];
__device__ __nv_bfloat16 g_wt1[2 * HD * 2 * HD];

// ---------------- tiling constants ----------------
// Swizzled tile: 128 rows x 128 bytes, addr = row*128 + ((c16 ^ (row&7))*16)
#define TILE 16384
#define STATS_OFF (6 * TILE)            // conv: 3 pipeline stages x (A,B)
#define CONV_SMEM (STATS_OFF + 1024)    // 99328
#define MLP_A 2560
#define MLP_SMEM (MLP_A + 4 * TILE)     // 68096

__device__ __forceinline__ float gelu_exact(float v) {
    return 0.5f * v * (1.0f + erff(v * 0.70710678118654752440f));
}
__device__ __forceinline__ uint32_t smem_u32(const void* p) {
    uint32_t a;
    asm("{ .reg .u64 t; cvta.to.shared.u64 t, %1; cvt.u32.u64 %0, t; }" : "=r"(a) : "l"(p));
    return a;
}
__device__ __forceinline__ uint32_t bfbits(__nv_bfloat16 h) {
    return (uint32_t)__bfloat16_as_ushort(h);
}
__device__ __forceinline__ uint32_t swzoff(int row, int c16) {
    return (uint32_t)(row * 128 + ((c16 ^ (row & 7)) * 16));
}
__device__ __forceinline__ void split2(float x, float y, uint32_t& hi, uint32_t& lo) {
    __nv_bfloat16 hx = __float2bfloat16(x), hy = __float2bfloat16(y);
    __nv_bfloat16 lx = __float2bfloat16(x - __bfloat162float(hx));
    __nv_bfloat16 ly = __float2bfloat16(y - __bfloat162float(hy));
    hi = bfbits(hx) | (bfbits(hy) << 16);
    lo = bfbits(lx) | (bfbits(ly) << 16);
}
__device__ __forceinline__ float2 recon2(uint32_t hb, uint32_t lb) {
    float2 h = __bfloat1622float2(*(__nv_bfloat162*)&hb);
    float2 l = __bfloat1622float2(*(__nv_bfloat162*)&lb);
    return make_float2(h.x + l.x, h.y + l.y);
}
__device__ __forceinline__ void ldmx4(uint32_t* r, uint32_t addr) {
    asm volatile("ldmatrix.sync.aligned.m8n8.x4.shared.b16 {%0,%1,%2,%3}, [%4];"
                 : "=r"(r[0]), "=r"(r[1]), "=r"(r[2]), "=r"(r[3]) : "r"(addr));
}
__device__ __forceinline__ void mma_bf16(float* c, const uint32_t* a, const uint32_t* b) {
    asm volatile(
        "mma.sync.aligned.m16n8k16.row.col.f32.bf16.bf16.f32 "
        "{%0,%1,%2,%3},{%4,%5,%6,%7},{%8,%9},{%0,%1,%2,%3};"
        : "+f"(c[0]), "+f"(c[1]), "+f"(c[2]), "+f"(c[3])
        : "r"(a[0]), "r"(a[1]), "r"(a[2]), "r"(a[3]), "r"(b[0]), "r"(b[1]));
}
__device__ __forceinline__ void cp16(uint32_t dst, const void* src, int sz) {
    asm volatile("cp.async.cg.shared.global [%0], [%1], 16, %2;"
                 :: "r"(dst), "l"(src), "r"(sz) : "memory");
}
__device__ __forceinline__ void cp_commit() {
    asm volatile("cp.async.commit_group;" ::: "memory");
}

// ---------------- CSR build ----------------
__global__ void hist_kernel(const int* __restrict__ ei, int* __restrict__ deg, int E) {
    int e = blockIdx.x * 256 + threadIdx.x;
    if (e < E) atomicAdd(&deg[ei[E + e]], 1);
}
__global__ void scan1(const int* __restrict__ deg, int* __restrict__ tmp,
                      int* __restrict__ part, int n) {
    __shared__ int warpsum[8];
    int b = blockIdx.x, t = threadIdx.x;
    int base = b * 1024 + t * 4;
    int v0 = (base + 0 < n) ? deg[base + 0] : 0;
    int v1 = (base + 1 < n) ? deg[base + 1] : 0;
    int v2 = (base + 2 < n) ? deg[base + 2] : 0;
    int v3 = (base + 3 < n) ? deg[base + 3] : 0;
    int s0 = v0, s1 = s0 + v1, s2 = s1 + v2, s3 = s2 + v3;
    int tot = s3;
#pragma unroll
    for (int d = 1; d < 32; d <<= 1) {
        int u = __shfl_up_sync(0xFFFFFFFF, tot, d);
        if ((t & 31) >= d) tot += u;
    }
    if ((t & 31) == 31) warpsum[t >> 5] = tot;
    __syncthreads();
    if (t == 0) {
        int r = 0;
#pragma unroll
        for (int i = 0; i < 8; i++) { int x = warpsum[i]; warpsum[i] = r; r += x; }
        part[b] = r;
    }
    __syncthreads();
    int excl = warpsum[t >> 5] + (tot - s3);
    if (base + 0 <= n) tmp[base + 0] = excl;
    if (base + 1 <= n) tmp[base + 1] = excl + s0;
    if (base + 2 <= n) tmp[base + 2] = excl + s1;
    if (base + 3 <= n) tmp[base + 3] = excl + s2;
}
__global__ void scan2(int* part, int nb) {
    if (threadIdx.x == 0) {
        int r = 0;
        for (int i = 0; i < nb; i++) { int x = part[i]; part[i] = r; r += x; }
    }
}
__global__ void scan3(const int* __restrict__ tmp, const int* __restrict__ part,
                      int* __restrict__ rowptr, int* __restrict__ cursor, int n, int E) {
    int i = blockIdx.x * 256 + threadIdx.x;
    if (i < n) {
        int v = tmp[i] + part[i >> 10];
        rowptr[i] = v;
        cursor[i] = v;
    }
    if (i == n) rowptr[n] = E;
}
__global__ void fill_csr(const int* __restrict__ ei, const float* __restrict__ ea,
                         int* __restrict__ cursor, int* __restrict__ csrc,
                         float* __restrict__ csw, int E) {
    int e = blockIdx.x * 256 + threadIdx.x;
    if (e >= E) return;
    int d = ei[E + e];
    int pos = atomicAdd(&cursor[d], 1);
    csrc[pos] = ei[e];
    csw[pos] = ea[e];
}

// ---------------- split x + zero deg ----------------
__global__ void split_x(const float4* __restrict__ x4, uint2* __restrict__ xhi,
                        uint2* __restrict__ xlo, int* __restrict__ deg, int n32, int n) {
    int i = blockIdx.x * 256 + threadIdx.x;
    if (i < n) deg[i] = 0;
    if (i >= n32) return;
    float4 v = x4[i];
    uint32_t h0, l0, h1, l1;
    split2(v.x, v.y, h0, l0);
    split2(v.z, v.w, h1, l1);
    xhi[i] = make_uint2(h0, h1);
    xlo[i] = make_uint2(l0, l1);
}

// ---------------- CSR aggregation: warp per node ----------------
__global__ void agg_kernel(const uint2* __restrict__ xhi, const uint2* __restrict__ xlo,
                           const int* __restrict__ rowptr,
                           const int* __restrict__ csrc, const float* __restrict__ csw,
                           uint2* __restrict__ ahi, uint2* __restrict__ alo,
                           float* __restrict__ stats, int nn) {
    if (blockIdx.x == 0 && threadIdx.x < 2 * HD) stats[threadIdx.x] = 0.f;
    int node = (blockIdx.x * blockDim.x + threadIdx.x) >> 5;
    int lane = threadIdx.x & 31;
    if (node >= nn) return;
    int beg = rowptr[node], end = rowptr[node + 1];
    float4 acc = make_float4(0.f, 0.f, 0.f, 0.f);
    for (int e = beg; e < end; e++) {
        int s = __ldg(&csrc[e]);
        float w = __ldg(&csw[e]);
        uint2 vh = __ldg(&xhi[(size_t)s * 32 + lane]);
        uint2 vl = __ldg(&xlo[(size_t)s * 32 + lane]);
        float2 v01 = recon2(vh.x, vl.x);
        float2 v23 = recon2(vh.y, vl.y);
        acc.x += v01.x * w; acc.y += v01.y * w;
        acc.z += v23.x * w; acc.w += v23.y * w;
    }
    uint32_t h0, l0, h1, l1;
    split2(acc.x, acc.y, h0, l0);
    split2(acc.z, acc.w, h1, l1);
    ahi[(size_t)node * 32 + lane] = make_uint2(h0, h1);
    alo[(size_t)node * 32 + lane] = make_uint2(l0, l1);
}

// ---------------- weight prep (transpose + split) ----------------
__global__ void prep_w(const float* __restrict__ rel_w, const float* __restrict__ root_w,
                       const float* __restrict__ w1, int NC) {
    int idx = blockIdx.x * 256 + threadIdx.x;
    int convTotal = NC * 2 * HD * HD;
    if (idx < convTotal) {
        int l = idx / (2 * HD * HD);
        int rem = idx % (2 * HD * HD);
        int m = rem / (HD * HD);
        int r = rem % (HD * HD);
        int k = r >> 7, nn = r & 127;
        const float* W = m ? root_w : rel_w;
        float v = W[(size_t)l * HD * HD + k * HD + nn];
        __nv_bfloat16 hi = __float2bfloat16(v);
        __nv_bfloat16 lo = __float2bfloat16(v - __bfloat162float(hi));
        size_t base = ((size_t)(l * 2 + m) * 2) * HD * HD;
        g_wtc[base + nn * HD + k] = hi;
        g_wtc[base + HD * HD + nn * HD + k] = lo;
    } else if (idx < convTotal + 2 * HD * HD) {
        int r = idx - convTotal;
        int k = r >> 7, nn = r & 127;
        float v = w1[(size_t)k * HD + nn];
        __nv_bfloat16 hi = __float2bfloat16(v);
        __nv_bfloat16 lo = __float2bfloat16(v - __bfloat162float(hi));
        g_wt1[(size_t)nn * 256 + k] = hi;
        g_wt1[(size_t)HD * 2 * HD + nn * 256 + k] = lo;
    }
}

// ---------------- conv GEMM: 3-stage cp.async pipelined HMMA ----------------
// 6 logical stages x 2 k-chunks = 12 steps of K=64; buffers rotate mod 3.
__device__ __forceinline__ void conv_issue(
    int step, int row0, int n, uint32_t sm, int t,
    const char* Ah0, const char* Al0, const char* Ah1, const char* Al1,
    const char* Wrh, const char* Wrl, const char* Woh, const char* Wol) {
    int stage = step >> 1, kc = step & 1;
    const char* As;
    const char* Bs;
    switch (stage) {
        case 0: As = Ah0; Bs = Wrh; break;
        case 1: As = Al0; Bs = Wrh; break;
        case 2: As = Ah0; Bs = Wrl; break;
        case 3: As = Ah1; Bs = Woh; break;
        case 4: As = Al1; Bs = Woh; break;
        default: As = Ah1; Bs = Wol; break;
    }
    uint32_t buf = sm + (uint32_t)(step % 3) * (2 * TILE);
#pragma unroll
    for (int p = 0; p < 4; p++) {
        int idx = p * 256 + t;
        int r = idx >> 3, u = idx & 7;
        int gr = row0 + r;
        uint32_t o = swzoff(r, u);
        cp16(buf + o, As + (size_t)gr * 256 + kc * 128 + u * 16, (gr < n) ? 16 : 0);
        cp16(buf + TILE + o, Bs + (size_t)r * 256 + kc * 128 + u * 16, 16);
    }
}

__global__ void __launch_bounds__(256, 2) conv_mma(
    const char* __restrict__ Ah0, const char* __restrict__ Al0,
    const char* __restrict__ Ah1, const char* __restrict__ Al1,
    const char* __restrict__ Wrh, const char* __restrict__ Wrl,
    const char* __restrict__ Woh, const char* __restrict__ Wol,
    const float* __restrict__ bias, float* __restrict__ Hout,
    float* __restrict__ stats, int n) {
    extern __shared__ __align__(16) char smp[];
    uint32_t sm = smem_u32(smp);
    int t = threadIdx.x, wid = t >> 5, lane = t & 31;
    int row0 = blockIdx.x * 128;
    int mbase = (wid & 1) * 64, nbase = (wid >> 1) * 32;

    float c[4][4][4];
#pragma unroll
    for (int i = 0; i < 4; i++)
#pragma unroll
        for (int j = 0; j < 4; j++)
#pragma unroll
            for (int q = 0; q < 4; q++) c[i][j][q] = 0.f;

    int sub = lane >> 3, r8 = lane & 7;
    int rowA = mbase + r8 + ((sub & 1) << 3);     // +mt*16 ; row&7 == r8
    int rowB = nbase + ((sub >> 1) << 3) + r8;    // +bp*16 ; row&7 == r8
    int cA0 = sub >> 1, cB0 = sub & 1;

    conv_issue(0, row0, n, sm, t, Ah0, Al0, Ah1, Al1, Wrh, Wrl, Woh, Wol);
    cp_commit();
    conv_issue(1, row0, n, sm, t, Ah0, Al0, Ah1, Al1, Wrh, Wrl, Woh, Wol);
    cp_commit();
#pragma unroll
    for (int s = 0; s < 12; s++) {
        if (s < 10) {
            conv_issue(s + 2, row0, n, sm, t, Ah0, Al0, Ah1, Al1, Wrh, Wrl, Woh, Wol);
            cp_commit();
            asm volatile("cp.async.wait_group 2;" ::: "memory");
        } else if (s == 10) {
            asm volatile("cp.async.wait_group 1;" ::: "memory");
        } else {
            asm volatile("cp.async.wait_group 0;" ::: "memory");
        }
        __syncthreads();
        uint32_t bufA = sm + (uint32_t)(s % 3) * (2 * TILE);
        uint32_t bufB = bufA + TILE;
#pragma unroll
        for (int ks = 0; ks < 4; ks++) {
            int cA = ((cA0 + 2 * ks) ^ r8) * 16;
            int cB = ((cB0 + 2 * ks) ^ r8) * 16;
            uint32_t a[4][4], b[8];
#pragma unroll
            for (int mt = 0; mt < 4; mt++)
                ldmx4(a[mt], bufA + (uint32_t)((rowA + mt * 16) * 128 + cA));
#pragma unroll
            for (int bp = 0; bp < 2; bp++)
                ldmx4(b + bp * 4, bufB + (uint32_t)((rowB + bp * 16) * 128 + cB));
#pragma unroll
            for (int mt = 0; mt < 4; mt++)
#pragma unroll
                for (int nt = 0; nt < 4; nt++) mma_bf16(c[mt][nt], a[mt], b + nt * 2);
        }
        __syncthreads();
    }

    // Epilogue: +bias, gelu, store, fused BN stats
    if (t < 128) {
        *(float*)(smp + STATS_OFF + t * 4) = 0.f;
        *(float*)(smp + STATS_OFF + 512 + t * 4) = 0.f;
    }
    __syncthreads();
    int g = lane >> 2, tq = lane & 3;
    float bv[8];
#pragma unroll
    for (int nt = 0; nt < 4; nt++) {
        bv[nt * 2 + 0] = __ldg(&bias[nbase + nt * 8 + tq * 2 + 0]);
        bv[nt * 2 + 1] = __ldg(&bias[nbase + nt * 8 + tq * 2 + 1]);
    }
    float colsum[8], colsq[8];
#pragma unroll
    for (int j = 0; j < 8; j++) { colsum[j] = 0.f; colsq[j] = 0.f; }
#pragma unroll
    for (int mt = 0; mt < 4; mt++) {
        int gr0 = row0 + mbase + mt * 16 + g, gr1 = gr0 + 8;
#pragma unroll
        for (int nt = 0; nt < 4; nt++) {
            int cb = nbase + nt * 8 + tq * 2;
            if (gr0 < n) {
                float o0 = gelu_exact(c[mt][nt][0] + bv[nt * 2]);
                float o1 = gelu_exact(c[mt][nt][1] + bv[nt * 2 + 1]);
                *(float2*)(Hout + (size_t)gr0 * HD + cb) = make_float2(o0, o1);
                colsum[nt * 2] += o0; colsq[nt * 2] += o0 * o0;
                colsum[nt * 2 + 1] += o1; colsq[nt * 2 + 1] += o1 * o1;
            }
            if (gr1 < n) {
                float o2 = gelu_exact(c[mt][nt][2] + bv[nt * 2]);
                float o3 = gelu_exact(c[mt][nt][3] + bv[nt * 2 + 1]);
                *(float2*)(Hout + (size_t)gr1 * HD + cb) = make_float2(o2, o3);
                colsum[nt * 2] += o2; colsq[nt * 2] += o2 * o2;
                colsum[nt * 2 + 1] += o3; colsq[nt * 2 + 1] += o3 * o3;
            }
        }
    }
#pragma unroll
    for (int j = 0; j < 8; j++) {
        float v = colsum[j], w = colsq[j];
        v += __shfl_down_sync(0xFFFFFFFF, v, 16); w += __shfl_down_sync(0xFFFFFFFF, w, 16);
        v += __shfl_down_sync(0xFFFFFFFF, v, 8);  w += __shfl_down_sync(0xFFFFFFFF, w, 8);
        v += __shfl_down_sync(0xFFFFFFFF, v, 4);  w += __shfl_down_sync(0xFFFFFFFF, w, 4);
        if (lane < 4) {
            int cb = nbase + (j >> 1) * 8 + lane * 2 + (j & 1);
            atomicAdd((float*)(smp + STATS_OFF + cb * 4), v);
            atomicAdd((float*)(smp + STATS_OFF + 512 + cb * 4), w);
        }
    }
    __syncthreads();
    if (t < 128) {
        atomicAdd(&stats[t], *(float*)(smp + STATS_OFF + t * 4));
        atomicAdd(&stats[HD + t], *(float*)(smp + STATS_OFF + 512 + t * 4));
    }
}

// ---------------- BN normalize -> emit split bf16 ----------------
__global__ void bn_kernel(const float4* __restrict__ h4, const float* __restrict__ stats,
                          const float* __restrict__ g, const float* __restrict__ b,
                          uint2* __restrict__ xhi, uint2* __restrict__ xlo, int n) {
    int i = blockIdx.x * blockDim.x + threadIdx.x;
    int total = n * 32;
    if (i >= total) return;
    int c4 = i & 31;
    float invN = 1.0f / (float)n;
    float4 s = ((const float4*)stats)[c4];
    float4 q = ((const float4*)stats)[32 + c4];
    float4 gg = ((const float4*)g)[c4];
    float4 bb = ((const float4*)b)[c4];
    float m0 = s.x * invN, m1 = s.y * invN, m2 = s.z * invN, m3 = s.w * invN;
    float sc0 = rsqrtf(fmaxf(q.x * invN - m0 * m0, 0.f) + 1e-5f) * gg.x;
    float sc1 = rsqrtf(fmaxf(q.y * invN - m1 * m1, 0.f) + 1e-5f) * gg.y;
    float sc2 = rsqrtf(fmaxf(q.z * invN - m2 * m2, 0.f) + 1e-5f) * gg.z;
    float sc3 = rsqrtf(fmaxf(q.w * invN - m3 * m3, 0.f) + 1e-5f) * gg.w;
    float4 h = h4[i];
    float ox = (h.x - m0) * sc0 + bb.x;
    float oy = (h.y - m1) * sc1 + bb.y;
    float oz = (h.z - m2) * sc2 + bb.z;
    float ow = (h.w - m3) * sc3 + bb.w;
    uint32_t h0, l0, h1, l1;
    split2(ox, oy, h0, l0);
    split2(oz, ow, h1, l1);
    xhi[i] = make_uint2(h0, h1);
    xlo[i] = make_uint2(l0, l1);
}

// ---------------- edge MLP (HMMA, swizzled tiles) ----------------
__global__ void __launch_bounds__(256, 2) mlp_mma(
    const char* __restrict__ Xhi, const char* __restrict__ Xlo,
    const int* __restrict__ eli,
    const __nv_bfloat16* __restrict__ W1h, const __nv_bfloat16* __restrict__ W1l,
    const float* __restrict__ B1, const float* __restrict__ W2,
    const float* __restrict__ B2, float* __restrict__ out, int EQ) {
    extern __shared__ __align__(16) char smp[];
    uint32_t sm = smem_u32(smp);
    int t = threadIdx.x, wid = t >> 5, lane = t & 31;
    int row0 = blockIdx.x * 128;
    int mbase = (wid & 1) * 64, nbase = (wid >> 1) * 32;

    if (t < HD) {
        *(float*)(smp + t * 4) = B1[t];
        *(float*)(smp + 512 + t * 4) = W2[t];
        *(float*)(smp + 1024 + t * 4) = 0.f;
        int gr = row0 + t;
        int e = (gr < EQ) ? gr : 0;
        *(int*)(smp + 1536 + t * 4) = eli[e];
        *(int*)(smp + 2048 + t * 4) = eli[EQ + e];
    }

    float c[4][4][4];
#pragma unroll
    for (int i = 0; i < 4; i++)
#pragma unroll
        for (int j = 0; j < 4; j++)
#pragma unroll
            for (int q = 0; q < 4; q++) c[i][j][q] = 0.f;

    int sub = lane >> 3, r8 = lane & 7;
    int rowA = mbase + r8 + ((sub & 1) << 3);
    int rowB = nbase + ((sub >> 1) << 3) + r8;
    int cA0 = sub >> 1, cB0 = sub & 1;

    for (int ch = 0; ch < 4; ch++) {
        int idxOff = (ch < 2) ? 1536 : 2048;
        int kc = ch & 1;
        __syncthreads();
#pragma unroll
        for (int p = 0; p < 4; p++) {
            int idx = p * 256 + t;
            int r = idx >> 3, u = idx & 7;
            int node = *(const int*)(smp + idxOff + r * 4);
            uint32_t o = swzoff(r, u);
            uint4 vh = *(const uint4*)(Xhi + (size_t)node * 256 + kc * 128 + u * 16);
            uint4 vl = *(const uint4*)(Xlo + (size_t)node * 256 + kc * 128 + u * 16);
            *(uint4*)(smp + MLP_A + o) = vh;
            *(uint4*)(smp + MLP_A + TILE + o) = vl;
        }
#pragma unroll
        for (int p = 0; p < 4; p++) {
            int lin = p * 256 + t;
            int nn = lin >> 3, q = lin & 7;
            uint32_t o = swzoff(nn, q);
            *(uint4*)(smp + MLP_A + 2 * TILE + o) =
                *(const uint4*)(W1h + (size_t)nn * 256 + ch * 64 + q * 8);
            *(uint4*)(smp + MLP_A + 3 * TILE + o) =
                *(const uint4*)(W1l + (size_t)nn * 256 + ch * 64 + q * 8);
        }
        __syncthreads();
#pragma unroll
        for (int ps = 0; ps < 3; ps++) {
            uint32_t Ab = sm + MLP_A + ((ps == 1) ? TILE : 0);
            uint32_t Bb = sm + MLP_A + 2 * TILE + ((ps == 2) ? TILE : 0);
#pragma unroll
            for (int ks = 0; ks < 4; ks++) {
                int cA = ((cA0 + 2 * ks) ^ r8) * 16;
                int cB = ((cB0 + 2 * ks) ^ r8) * 16;
                uint32_t a[4][4], b[8];
#pragma unroll
                for (int mt = 0; mt < 4; mt++)
                    ldmx4(a[mt], Ab + (uint32_t)((rowA + mt * 16) * 128 + cA));
#pragma unroll
                for (int bp = 0; bp < 2; bp++)
                    ldmx4(b + bp * 4, Bb + (uint32_t)((rowB + bp * 16) * 128 + cB));
#pragma unroll
                for (int mt = 0; mt < 4; mt++)
#pragma unroll
                    for (int nt = 0; nt < 4; nt++) mma_bf16(c[mt][nt], a[mt], b + nt * 2);
            }
        }
    }

    int g = lane >> 2, tq = lane & 3;
#pragma unroll
    for (int mt = 0; mt < 4; mt++) {
        float p0 = 0.f, p1 = 0.f;
#pragma unroll
        for (int nt = 0; nt < 4; nt++) {
            int cb = nbase + nt * 8 + tq * 2;
            float2 bvv = *(float2*)(smp + cb * 4);
            float2 wv = *(float2*)(smp + 512 + cb * 4);
            p0 += gelu_exact(c[mt][nt][0] + bvv.x) * wv.x
                + gelu_exact(c[mt][nt][1] + bvv.y) * wv.y;
            p1 += gelu_exact(c[mt][nt][2] + bvv.x) * wv.x
                + gelu_exact(c[mt][nt][3] + bvv.y) * wv.y;
        }
        p0 += __shfl_xor_sync(0xFFFFFFFF, p0, 1);
        p0 += __shfl_xor_sync(0xFFFFFFFF, p0, 2);
        p1 += __shfl_xor_sync(0xFFFFFFFF, p1, 1);
        p1 += __shfl_xor_sync(0xFFFFFFFF, p1, 2);
        if (tq == 0) {
            int lr = mbase + mt * 16 + g;
            atomicAdd((float*)(smp + 1024 + lr * 4), p0);
            atomicAdd((float*)(smp + 1024 + (lr + 8) * 4), p1);
        }
    }
    __syncthreads();
    if (t < 128) {
        int gr = row0 + t;
        if (gr < EQ) {
            float z = *(float*)(smp + 1024 + t * 4) + B2[0];
            out[gr] = 1.0f / (1.0f + expf(-z));
        }
    }
}

// ---------------------------------------------------------------------------
extern "C" void kernel_launch(void* const* d_in, const int* in_sizes, int n_in,
                              void* d_out, int out_size) {
    const float* x      = (const float*)d_in[0];
    const int*   ei     = (const int*)d_in[1];
    const float* ea     = (const float*)d_in[2];
    const int*   eli    = (const int*)d_in[3];
    const float* rel_w  = (const float*)d_in[4];
    const float* rel_b  = (const float*)d_in[5];
    const float* root_w = (const float*)d_in[6];
    const float* bn_g   = (const float*)d_in[7];
    const float* bn_b   = (const float*)d_in[8];
    const float* w1     = (const float*)d_in[9];
    const float* b1     = (const float*)d_in[10];
    const float* w2     = (const float*)d_in[11];
    const float* b2     = (const float*)d_in[12];

    int N  = in_sizes[0] / HD;
    int E  = in_sizes[1] / 2;
    int EQ = in_sizes[3] / 2;
    int NC = in_sizes[4] / (HD * HD);

    float *hbuf, *stats;
    __nv_bfloat16 *ahi, *alo, *xhi, *xlo, *wtc, *wt1;
    int *deg, *tmp, *part, *rowptr, *cursor, *csrc;
    float *csw;
    cudaGetSymbolAddress((void**)&hbuf,   g_h);
    cudaGetSymbolAddress((void**)&stats,  g_stats);
    cudaGetSymbolAddress((void**)&ahi,    g_agg_hi);
    cudaGetSymbolAddress((void**)&alo,    g_agg_lo);
    cudaGetSymbolAddress((void**)&xhi,    g_xhi);
    cudaGetSymbolAddress((void**)&xlo,    g_xlo);
    cudaGetSymbolAddress((void**)&deg,    g_deg);
    cudaGetSymbolAddress((void**)&tmp,    g_tmp);
    cudaGetSymbolAddress((void**)&part,   g_part);
    cudaGetSymbolAddress((void**)&rowptr, g_rowptr);
    cudaGetSymbolAddress((void**)&cursor, g_cursor);
    cudaGetSymbolAddress((void**)&csrc,   g_csrc);
    cudaGetSymbolAddress((void**)&csw,    g_csw);
    cudaGetSymbolAddress((void**)&wtc,    g_wtc);
    cudaGetSymbolAddress((void**)&wt1,    g_wt1);

    cudaFuncSetAttribute(conv_mma, cudaFuncAttributeMaxDynamicSharedMemorySize, CONV_SMEM);
    cudaFuncSetAttribute(mlp_mma,  cudaFuncAttributeMaxDynamicSharedMemorySize, MLP_SMEM);

    int n32 = N * 32;
    int pb = (NC * 2 * HD * HD + 2 * HD * HD + 255) / 256;
    int NB = (N + 1023) / 1024;
    int gb = (N + 127) / 128;
    int mb = (EQ + 127) / 128;

    prep_w<<<pb, 256>>>(rel_w, root_w, w1, NC);
    split_x<<<(n32 + 255) / 256, 256>>>((const float4*)x, (uint2*)xhi, (uint2*)xlo,
                                        deg, n32, N);
    hist_kernel<<<(E + 255) / 256, 256>>>(ei, deg, E);
    scan1<<<NB, 256>>>(deg, tmp, part, N);
    scan2<<<1, 32>>>(part, NB);
    scan3<<<(N + 256) / 256, 256>>>(tmp, part, rowptr, cursor, N, E);
    fill_csr<<<(E + 255) / 256, 256>>>(ei, ea, cursor, csrc, csw, E);

    for (int l = 0; l < NC; l++) {
        agg_kernel<<<(N + 7) / 8, 256>>>((const uint2*)xhi, (const uint2*)xlo,
                                         rowptr, csrc, csw,
                                         (uint2*)ahi, (uint2*)alo, stats, N);
        size_t wb = (size_t)(l * 2) * 2 * HD * HD;
        conv_mma<<<gb, 256, CONV_SMEM>>>(
            (const char*)ahi, (const char*)alo, (const char*)xhi, (const char*)xlo,
            (const char*)(wtc + wb), (const char*)(wtc + wb + HD * HD),
            (const char*)(wtc + wb + 2 * HD * HD), (const char*)(wtc + wb + 3 * HD * HD),
            rel_b + (size_t)l * HD, hbuf, stats, N);
        bn_kernel<<<(n32 + 255) / 256, 256>>>((const float4*)hbuf, stats,
                                              bn_g + (size_t)l * HD, bn_b + (size_t)l * HD,
                                              (uint2*)xhi, (uint2*)xlo, N);
    }
    mlp_mma<<<mb, 256, MLP_SMEM>>>((const char*)xhi, (const char*)xlo, eli,
                                   wt1, wt1 + (size_t)HD * 2 * HD,
                                   b1, w2, b2, (float*)d_out, EQ);
}